// round 7
// baseline (speedup 1.0000x reference)
#include <cuda_runtime.h>
#include <cuda_fp16.h>
#include <cstdint>
#include <cstddef>

// ---------------- problem constants ----------------
#define SEQA   4096
#define BATCH  8
#define DM     1024
#define MROWS  (SEQA*BATCH)          // 32768
#define NELEM_W   ((size_t)DM*DM)    // 1048576

static __device__ __forceinline__ float inv_alpha() { return 1.0f/1.5f; }
#define SCORE_SCALE 0.125f           // 1/sqrt(64)

// ---------------- scratch (device globals; allocation-free) ----------------
__device__ __half g_wh[4][DM*DM];
__device__ float g_q[MROWS*DM];
__device__ float g_k[MROWS*DM];
__device__ float g_v[MROWS*DM];
__device__ float g_x2[MROWS*DM];

// ---------------- PTX helpers (baseline ISA only: sm_80-era) ----------------
__device__ __forceinline__ uint32_t smem_u32(const void* p) {
    uint32_t r;
    asm("{ .reg .u64 t; cvta.to.shared.u64 t, %1; cvt.u32.u64 %0, t; }"
        : "=r"(r) : "l"(p));
    return r;
}
__device__ __forceinline__ void cpasync16(uint32_t saddr, const void* g) {
    asm volatile("cp.async.cg.shared.global [%0], [%1], 16;"
                 :: "r"(saddr), "l"(g) : "memory");
}
__device__ __forceinline__ void cp_commit() {
    asm volatile("cp.async.commit_group;" ::: "memory");
}
template<int N> __device__ __forceinline__ void cp_wait() {
    asm volatile("cp.async.wait_group %0;" :: "n"(N) : "memory");
}
__device__ __forceinline__ void ldsm4(uint32_t* r, uint32_t addr) {
    asm volatile("ldmatrix.sync.aligned.m8n8.x4.shared.b16 {%0,%1,%2,%3}, [%4];"
                 : "=r"(r[0]), "=r"(r[1]), "=r"(r[2]), "=r"(r[3]) : "r"(addr));
}
__device__ __forceinline__ void mma16816(float* d, const uint32_t* a, const uint32_t* b) {
    asm volatile(
        "mma.sync.aligned.m16n8k16.row.col.f32.f16.f16.f32 "
        "{%0,%1,%2,%3}, {%4,%5,%6,%7}, {%8,%9}, {%0,%1,%2,%3};"
        : "+f"(d[0]), "+f"(d[1]), "+f"(d[2]), "+f"(d[3])
        : "r"(a[0]), "r"(a[1]), "r"(a[2]), "r"(a[3]), "r"(b[0]), "r"(b[1]));
}

// ---------------- weight conversion: fp32 -> fp16 (4 matrices, one launch) ----
__global__ void __launch_bounds__(256) conv4_fp16_kernel(
    const float4* __restrict__ w0, const float4* __restrict__ w1,
    const float4* __restrict__ w2, const float4* __restrict__ w3,
    uint4* __restrict__ h, int n8)
{
    int i = blockIdx.x * blockDim.x + threadIdx.x;
    if (i >= n8) return;
    const int w = blockIdx.y;
    const float4* x = (w == 0) ? w0 : (w == 1) ? w1 : (w == 2) ? w2 : w3;
    uint4* out = h + (size_t)w * n8;

    float4 a = x[2*i];
    float4 b = x[2*i+1];
    float v[8] = {a.x, a.y, a.z, a.w, b.x, b.y, b.z, b.w};
    uint32_t hw[4];
#pragma unroll
    for (int j = 0; j < 4; j++) {
        __half2 hp = __floats2half2_rn(v[2*j], v[2*j+1]);
        hw[j] = *reinterpret_cast<uint32_t*>(&hp);
    }
    out[i] = make_uint4(hw[0], hw[1], hw[2], hw[3]);
}

// ---------------- fused split-fp16 HMMA GEMM, fp32 A input ----------------
// C[32768,1024] = A_fp32 @ Bh^T + bias, computed as (Ahi + Alo) @ Bh with the
// hi/lo fp16 split done on the fly in the A loader (LDG fp32 -> cvt -> STS).
// Per k-chunk (BK=64) BOTH segments are mma'd against ONE B staging:
// B smem traffic halved, syncs per mma halved vs the 2-segment-pass version.
// CTA tile 128x256, 8 warps = 2(m) x 4(n), warp tile 64x64.
// B: 4-stage cp.async pipeline (128KB). A: 2 double-buffered hi+lo bufs (64KB).
#define BM 128
#define BN 256
#define BK 64
#define BSTAGES 4
#define A_HL 16384                    // one hi or lo buffer: 128 rows x 128B
#define A_BUF 32768                   // hi+lo pair
#define B_STAGE 32768                 // 256 rows x 128B
#define GEMM_SMEM (2*A_BUF + BSTAGES*B_STAGE)   // 196608
#define NCH 16                        // K=1024 / BK

__global__ void __launch_bounds__(256, 1) gemm_f32a(
    const float* __restrict__ A, const __half* __restrict__ Bh,
    const float* __restrict__ bias, float* __restrict__ C)
{
    extern __shared__ __align__(1024) char smem[];
    const uint32_t sb = smem_u32(smem);
    const int tid  = threadIdx.x;
    const int lane = tid & 31;
    const int wid  = tid >> 5;
    const int wm   = wid >> 2;       // 0..1 (M 64 each)
    const int wn   = wid & 3;        // 0..3 (N 64 each)
    const int row0 = blockIdx.y * BM;
    const int col0 = blockIdx.x * BN;

    // B loader lanes: 256 rows x 128B, thread -> (row lr, 16B col lc)
    const int lr = tid >> 3;         // 0..31
    const int lc = tid & 7;          // 0..7

    // A loader lanes: 128 rows x 256B fp32; thread -> (row ar, 128B half ah)
    const int ar = tid >> 1;         // 0..127
    const int ah = tid & 1;          // 0..1

    float acc[4][8][4];
#pragma unroll
    for (int a = 0; a < 4; a++)
#pragma unroll
        for (int b = 0; b < 8; b++)
#pragma unroll
            for (int c = 0; c < 4; c++) acc[a][b][c] = 0.0f;

    const float* Arow = A + (size_t)(row0 + ar) * DM + ah * 32;

    // in-flight fp32 A chunk (32 floats = 8 float4 = 32 regs)
    float4 areg[8];

    auto ldg_a = [&](int ch) {
        const float4* src = (const float4*)(Arow + ch * BK);
#pragma unroll
        for (int j = 0; j < 8; j++) areg[j] = src[j];
    };
    // convert areg -> hi/lo fp16 and store swizzled into A buffer `b`
    auto sts_a = [&](int b) {
        const uint32_t hiB = sb + (uint32_t)b * A_BUF;
        const uint32_t loB = hiB + A_HL;
#pragma unroll
        for (int j = 0; j < 4; j++) {
            float4 v0 = areg[2*j], v1 = areg[2*j+1];
            __half2 h0 = __floats2half2_rn(v0.x, v0.y);
            __half2 h1 = __floats2half2_rn(v0.z, v0.w);
            __half2 h2 = __floats2half2_rn(v1.x, v1.y);
            __half2 h3 = __floats2half2_rn(v1.z, v1.w);
            __half2 l0 = __floats2half2_rn(v0.x - __low2float(h0), v0.y - __high2float(h0));
            __half2 l1 = __floats2half2_rn(v0.z - __low2float(h1), v0.w - __high2float(h1));
            __half2 l2 = __floats2half2_rn(v1.x - __low2float(h2), v1.y - __high2float(h2));
            __half2 l3 = __floats2half2_rn(v1.z - __low2float(h3), v1.w - __high2float(h3));
            int u = ah * 4 + j;                       // 16B unit within 128B row
            uint32_t sw = (uint32_t)(ar * 128) + ((uint32_t)(u ^ (ar & 7)) << 4);
            *(uint4*)(smem + (hiB - sb) + sw) = make_uint4(
                *(uint32_t*)&h0, *(uint32_t*)&h1, *(uint32_t*)&h2, *(uint32_t*)&h3);
            *(uint4*)(smem + (loB - sb) + sw) = make_uint4(
                *(uint32_t*)&l0, *(uint32_t*)&l1, *(uint32_t*)&l2, *(uint32_t*)&l3);
        }
    };
    auto load_b = [&](int s, int ch) {
        const uint32_t sbB = sb + 2*A_BUF + (uint32_t)s * B_STAGE;
        const int ksub = ch * BK;
#pragma unroll
        for (int rep = 0; rep < 8; rep++) {          // 256 rows
            int r = lr + rep * 32;
            uint32_t sw = (uint32_t)(r * 128) + ((uint32_t)(lc ^ (r & 7)) << 4);
            cpasync16(sbB + sw, Bh + (size_t)(col0 + r) * DM + ksub + lc * 8);
        }
    };

    // ---- prologue ----
    ldg_a(0);
#pragma unroll
    for (int s = 0; s < BSTAGES - 1; s++) { load_b(s, s); cp_commit(); }
    sts_a(0);                                        // into A buf 0
    ldg_a(1);

    for (int ch = 0; ch < NCH; ch++) {
        cp_wait<BSTAGES - 2>();
        __syncthreads();                             // B(ch) + A(ch) smem visible

        // keep memory moving before compute
        if (ch + 1 < NCH) sts_a((ch + 1) & 1);       // consumes areg = chunk ch+1
        if (ch + 2 < NCH) ldg_a(ch + 2);             // refills areg (WAR after STS)
        if (ch + BSTAGES - 1 < NCH) load_b((ch + BSTAGES - 1) % BSTAGES, ch + BSTAGES - 1);
        cp_commit();                                 // uniform group accounting

        const uint32_t aHi = sb + (uint32_t)(ch & 1) * A_BUF;
        const uint32_t aLo = aHi + A_HL;
        const uint32_t sbB = sb + 2*A_BUF + (uint32_t)(ch % BSTAGES) * B_STAGE;

#pragma unroll
        for (int k16 = 0; k16 < 4; k16++) {
            uint32_t bfrag[4][4];
#pragma unroll
            for (int nb = 0; nb < 4; nb++) {
                int r   = wn * 64 + nb * 16 + (lane & 7) + ((lane & 16) ? 8 : 0);
                int c16 = k16 * 2 + ((lane >> 3) & 1);
                ldsm4(bfrag[nb], sbB + (uint32_t)(r * 128) + ((uint32_t)(c16 ^ (r & 7)) << 4));
            }
            uint32_t afragH[4][4], afragL[4][4];
#pragma unroll
            for (int mi = 0; mi < 4; mi++) {
                int r   = wm * 64 + mi * 16 + (lane & 15);
                int c16 = k16 * 2 + (lane >> 4);
                uint32_t sw = (uint32_t)(r * 128) + ((uint32_t)(c16 ^ (r & 7)) << 4);
                ldsm4(afragH[mi], aHi + sw);
                ldsm4(afragL[mi], aLo + sw);
            }
#pragma unroll
            for (int mi = 0; mi < 4; mi++)
#pragma unroll
                for (int ni = 0; ni < 8; ni++)
                    mma16816(acc[mi][ni], afragH[mi], &bfrag[ni >> 1][(ni & 1) * 2]);
#pragma unroll
            for (int mi = 0; mi < 4; mi++)
#pragma unroll
                for (int ni = 0; ni < 8; ni++)
                    mma16816(acc[mi][ni], afragL[mi], &bfrag[ni >> 1][(ni & 1) * 2]);
        }
    }

    // ---- epilogue: bias add + fp32 store ----
    const int m_base = row0 + wm * 64;
    const int n_base = col0 + wn * 64;
    const int qr = lane >> 2;
    const int qc = (lane & 3) * 2;
#pragma unroll
    for (int ni = 0; ni < 8; ni++) {
        int colg = n_base + ni * 8 + qc;
        float bx = bias[colg], by = bias[colg + 1];
#pragma unroll
        for (int mi = 0; mi < 4; mi++) {
            int rg = m_base + mi * 16 + qr;
            float2 v0 = make_float2(acc[mi][ni][0] + bx, acc[mi][ni][1] + by);
            float2 v1 = make_float2(acc[mi][ni][2] + bx, acc[mi][ni][3] + by);
            *(float2*)(C + (size_t)rg * DM + colg)       = v0;
            *(float2*)(C + (size_t)(rg + 8) * DM + colg) = v1;
        }
    }
}

// ---------------- head-mixing sparsemax attention ----------------
// One block per (a,b) token. Output written (fp32) directly into the
// (B,H,A,hd)->(B,4096,1024) reshape layout: GEMM-row m2 = (h*256 + a/16)*8 + b,
// col = (a%16)*64 + d. The final GEMM splits it to fp16 hi/lo itself.
__global__ void __launch_bounds__(256) attn_kernel(
    const float* __restrict__ Q, const float* __restrict__ K, const float* __restrict__ V,
    float* __restrict__ x2)
{
    __shared__ float Qs[1024];
    __shared__ float Ks[16 * 65];
    __shared__ float Vs[1024];
    __shared__ float Ps[256];

    const int m = blockIdx.x;
    const int a = m >> 3, b = m & 7;
    const int t = threadIdx.x;

    {
        float4 q4 = ((const float4*)(Q + (size_t)m * DM))[t];
        ((float4*)Qs)[t] = q4;
        float4 k4 = ((const float4*)(K + (size_t)m * DM))[t];
        int ci = t * 4;
        int krow = ci >> 6, kcol = ci & 63;
        Ks[krow * 65 + kcol]     = k4.x;
        Ks[krow * 65 + kcol + 1] = k4.y;
        Ks[krow * 65 + kcol + 2] = k4.z;
        Ks[krow * 65 + kcol + 3] = k4.w;
        float4 v4 = ((const float4*)(V + (size_t)m * DM))[t];
        ((float4*)Vs)[t] = v4;
    }
    __syncthreads();

    {
        int h = t >> 4, g = t & 15;
        float accv = 0.0f;
#pragma unroll
        for (int i = 0; i < 64; i++)
            accv = fmaf(Qs[h * 64 + i], Ks[g * 65 + i], accv);
        Ps[t] = accv * SCORE_SCALE;
    }
    __syncthreads();

    if (t < 16) {
        float z[16];
#pragma unroll
        for (int i = 0; i < 16; i++) z[i] = Ps[t * 16 + i] * inv_alpha();
#pragma unroll
        for (int k = 2; k <= 16; k <<= 1) {
#pragma unroll
            for (int j = k >> 1; j > 0; j >>= 1) {
#pragma unroll
                for (int i = 0; i < 16; i++) {
                    int l = i ^ j;
                    if (l > i) {
                        bool up = ((i & k) == 0);
                        float zi = z[i], zl = z[l];
                        bool sw = up ? (zi > zl) : (zi < zl);
                        if (sw) { z[i] = zl; z[l] = zi; }
                    }
                }
            }
        }
        float cum = 0.0f, csel = 0.0f;
        int kc = 1;
#pragma unroll
        for (int r = 1; r <= 16; r++) {
            float v = z[16 - r];
            cum += v;
            if (v * (float)r > cum - 1.0f) { kc = r; csel = cum; }
        }
        float tau = (csel - 1.0f) / (float)kc;
#pragma unroll
        for (int i = 0; i < 16; i++) {
            float p = Ps[t * 16 + i] * inv_alpha() - tau;
            Ps[t * 16 + i] = p > 0.0f ? p : 0.0f;
        }
    }
    __syncthreads();

    {
        int h = t >> 4;
        int db = (t & 15) * 4;
        float o0 = 0, o1 = 0, o2 = 0, o3 = 0;
#pragma unroll
        for (int g = 0; g < 16; g++) {
            float p = Ps[h * 16 + g];
            const float* vr = Vs + g * 64 + db;
            o0 = fmaf(p, vr[0], o0);
            o1 = fmaf(p, vr[1], o1);
            o2 = fmaf(p, vr[2], o2);
            o3 = fmaf(p, vr[3], o3);
        }
        size_t m2  = ((size_t)(h * 256 + (a >> 4))) * 8 + (size_t)b;
        int    col = (a & 15) * 64 + db;
        *(float4*)(x2 + m2 * DM + col) = make_float4(o0, o1, o2, o3);
    }
}

// ---------------- launcher ----------------
extern "C" void kernel_launch(void* const* d_in, const int* in_sizes, int n_in,
                              void* d_out, int out_size)
{
    (void)in_sizes; (void)n_in; (void)out_size;

    void *pwh, *pq, *pk, *pv, *px2;
    cudaGetSymbolAddress(&pwh,  g_wh);
    cudaGetSymbolAddress(&pq,   g_q);
    cudaGetSymbolAddress(&pk,   g_k);
    cudaGetSymbolAddress(&pv,   g_v);
    cudaGetSymbolAddress(&px2,  g_x2);

    __half* wh  = (__half*)pwh;
    float* qbuf = (float*)pq;
    float* kbuf = (float*)pk;
    float* vbuf = (float*)pv;
    float* x2   = (float*)px2;

    cudaFuncSetAttribute(gemm_f32a, cudaFuncAttributeMaxDynamicSharedMemorySize, GEMM_SMEM);

    // 1) convert weights (Wq,Wk,Wv,Wo) to fp16 — one launch
    const int wN8 = (int)(NELEM_W / 8);
    conv4_fp16_kernel<<<dim3(wN8 / 256, 4), 256>>>(
        (const float4*)d_in[3], (const float4*)d_in[5],
        (const float4*)d_in[7], (const float4*)d_in[9],
        (uint4*)wh, wN8);

    // 2) Q/K/V projections straight from fp32 inputs (split fused into loader)
    dim3 ggrid(DM / BN, MROWS / BM);   // (4, 256)
    gemm_f32a<<<ggrid, 256, GEMM_SMEM>>>(
        (const float*)d_in[0], wh, (const float*)d_in[4], qbuf);
    gemm_f32a<<<ggrid, 256, GEMM_SMEM>>>(
        (const float*)d_in[1], wh + NELEM_W, (const float*)d_in[6], kbuf);
    gemm_f32a<<<ggrid, 256, GEMM_SMEM>>>(
        (const float*)d_in[2], wh + 2 * NELEM_W, (const float*)d_in[8], vbuf);

    // 3) sparsemax attention -> permuted X2 (fp32)
    attn_kernel<<<MROWS, 256>>>(qbuf, kbuf, vbuf, x2);

    // 4) output projection straight into d_out (split fused again)
    gemm_f32a<<<ggrid, 256, GEMM_SMEM>>>(
        x2, wh + 3 * NELEM_W, (const float*)d_in[10], (float*)d_out);
}

// round 8
// speedup vs baseline: 1.6299x; 1.6299x over previous
#include <cuda_runtime.h>
#include <cuda_fp16.h>
#include <cstdint>
#include <cstddef>

// ---------------- problem constants ----------------
#define SEQA   4096
#define BATCH  8
#define DM     1024
#define MROWS  (SEQA*BATCH)          // 32768
#define NELEM_ACT ((size_t)MROWS*DM) // 33554432
#define NELEM_W   ((size_t)DM*DM)    // 1048576

static __device__ __forceinline__ float inv_alpha() { return 1.0f/1.5f; }
#define SCORE_SCALE 0.125f           // 1/sqrt(64)

// ---------------- scratch (device globals; allocation-free) ----------------
__device__ __half g_ahi[3][MROWS*DM];
__device__ __half g_alo[3][MROWS*DM];
__device__ __half g_wh[4][DM*DM];
__device__ float g_q[MROWS*DM];
__device__ float g_k[MROWS*DM];
__device__ float g_v[MROWS*DM];
__device__ __half g_x2hi[MROWS*DM];
__device__ __half g_x2lo[MROWS*DM];

// ---------------- PTX helpers (baseline ISA only: sm_80-era) ----------------
__device__ __forceinline__ uint32_t smem_u32(const void* p) {
    uint32_t r;
    asm("{ .reg .u64 t; cvta.to.shared.u64 t, %1; cvt.u32.u64 %0, t; }"
        : "=r"(r) : "l"(p));
    return r;
}
__device__ __forceinline__ void cpasync16(uint32_t saddr, const void* g) {
    asm volatile("cp.async.cg.shared.global [%0], [%1], 16;"
                 :: "r"(saddr), "l"(g) : "memory");
}
__device__ __forceinline__ void cp_commit() {
    asm volatile("cp.async.commit_group;" ::: "memory");
}
template<int N> __device__ __forceinline__ void cp_wait() {
    asm volatile("cp.async.wait_group %0;" :: "n"(N) : "memory");
}
__device__ __forceinline__ void ldsm4(uint32_t* r, uint32_t addr) {
    asm volatile("ldmatrix.sync.aligned.m8n8.x4.shared.b16 {%0,%1,%2,%3}, [%4];"
                 : "=r"(r[0]), "=r"(r[1]), "=r"(r[2]), "=r"(r[3]) : "r"(addr));
}
__device__ __forceinline__ void mma16816(float* d, const uint32_t* a, const uint32_t* b) {
    asm volatile(
        "mma.sync.aligned.m16n8k16.row.col.f32.f16.f16.f32 "
        "{%0,%1,%2,%3}, {%4,%5,%6,%7}, {%8,%9}, {%0,%1,%2,%3};"
        : "+f"(d[0]), "+f"(d[1]), "+f"(d[2]), "+f"(d[3])
        : "r"(a[0]), "r"(a[1]), "r"(a[2]), "r"(a[3]), "r"(b[0]), "r"(b[1]));
}

// ---------------- fused split kernels: fp32 -> fp16 (hi[,lo]) ----------------
__global__ void __launch_bounds__(256) split3_fp16_kernel(
    const float4* __restrict__ x0, const float4* __restrict__ x1,
    const float4* __restrict__ x2,
    uint4* __restrict__ hi, uint4* __restrict__ lo, int n8)
{
    int i = blockIdx.x * blockDim.x + threadIdx.x;
    if (i >= n8) return;
    const int w = blockIdx.y;
    const float4* x = (w == 0) ? x0 : (w == 1) ? x1 : x2;
    uint4* hw4 = hi + (size_t)w * n8;
    uint4* lw4 = lo + (size_t)w * n8;

    float4 a = x[2*i];
    float4 b = x[2*i+1];
    float v[8] = {a.x, a.y, a.z, a.w, b.x, b.y, b.z, b.w};
    uint32_t hw[4], lw[4];
#pragma unroll
    for (int j = 0; j < 4; j++) {
        __half2 hp = __floats2half2_rn(v[2*j], v[2*j+1]);
        float l0 = v[2*j]   - __low2float(hp);
        float l1 = v[2*j+1] - __high2float(hp);
        __half2 lp = __floats2half2_rn(l0, l1);
        hw[j] = *reinterpret_cast<uint32_t*>(&hp);
        lw[j] = *reinterpret_cast<uint32_t*>(&lp);
    }
    hw4[i] = make_uint4(hw[0], hw[1], hw[2], hw[3]);
    lw4[i] = make_uint4(lw[0], lw[1], lw[2], lw[3]);
}

__global__ void __launch_bounds__(256) conv4_fp16_kernel(
    const float4* __restrict__ w0, const float4* __restrict__ w1,
    const float4* __restrict__ w2, const float4* __restrict__ w3,
    uint4* __restrict__ h, int n8)
{
    int i = blockIdx.x * blockDim.x + threadIdx.x;
    if (i >= n8) return;
    const int w = blockIdx.y;
    const float4* x = (w == 0) ? w0 : (w == 1) ? w1 : (w == 2) ? w2 : w3;
    uint4* out = h + (size_t)w * n8;

    float4 a = x[2*i];
    float4 b = x[2*i+1];
    float v[8] = {a.x, a.y, a.z, a.w, b.x, b.y, b.z, b.w};
    uint32_t hw[4];
#pragma unroll
    for (int j = 0; j < 4; j++) {
        __half2 hp = __floats2half2_rn(v[2*j], v[2*j+1]);
        hw[j] = *reinterpret_cast<uint32_t*>(&hp);
    }
    out[i] = make_uint4(hw[0], hw[1], hw[2], hw[3]);
}

// ---------------- HMMA split-fp16 GEMM, 2 CTAs/SM ----------------
// C[32768,1024] = (Ahi+Alo) @ Bh^T + bias. Effective K = 2*1024 via 2 segments.
// CTA tile 128x128, 4 warps = 2(m) x 2(n), warp tile 64x64, BK=64,
// 3-stage cp.async pipeline (96KB smem) -> 2 independent CTAs per SM so their
// barrier/wait bubbles interleave. Grid is M-fastest so one wave shares a B tile.
#define BM 128
#define BN 128
#define BK 64
#define STAGES 3
#define AB_STAGE 16384                 // 128 rows x 128B (each of A and B)
#define GEMM_SMEM (STAGES * 2 * AB_STAGE)   // 98304
#define NCH 32                         // 2 segs * 16 chunks

__global__ void __launch_bounds__(128, 2) gemm_hmma(
    const __half* __restrict__ Ahi, const __half* __restrict__ Alo,
    const __half* __restrict__ Bh,
    const float* __restrict__ bias, float* __restrict__ C)
{
    extern __shared__ __align__(1024) char smem[];
    const uint32_t sb = smem_u32(smem);
    const int tid  = threadIdx.x;
    const int lane = tid & 31;
    const int wid  = tid >> 5;        // 0..3
    const int wm   = wid >> 1;        // 0..1 (M 64 each)
    const int wn   = wid & 1;         // 0..1 (N 64 each)
    const int row0 = blockIdx.x * BM; // M fastest-varying
    const int col0 = blockIdx.y * BN;

    // loader lanes: 128 threads -> (row lr 0..15, 16B unit lc 0..7), 8 reps
    const int lr = tid >> 3;
    const int lc = tid & 7;

    float acc[4][8][4];
#pragma unroll
    for (int a = 0; a < 4; a++)
#pragma unroll
        for (int b = 0; b < 8; b++)
#pragma unroll
            for (int c = 0; c < 4; c++) acc[a][b][c] = 0.0f;

    auto load_stage = [&](int s, int ch) {
        const __half* As = (ch < 16) ? Ahi : Alo;
        const int ksub = (ch & 15) * BK;
        const uint32_t sa  = sb + (uint32_t)s * 2 * AB_STAGE;
        const uint32_t sbB = sa + AB_STAGE;
#pragma unroll
        for (int rep = 0; rep < 8; rep++) {
            int r = lr + rep * 16;
            uint32_t sw = (uint32_t)(r * 128) + ((uint32_t)(lc ^ (r & 7)) << 4);
            cpasync16(sa  + sw, As + (size_t)(row0 + r) * DM + ksub + lc * 8);
            cpasync16(sbB + sw, Bh + (size_t)(col0 + r) * DM + ksub + lc * 8);
        }
    };

    // prologue: fill STAGES-1 stages
#pragma unroll
    for (int s = 0; s < STAGES - 1; s++) { load_stage(s, s); cp_commit(); }

    for (int ch = 0; ch < NCH; ch++) {
        cp_wait<STAGES - 2>();
        __syncthreads();

        // issue next-stage loads BEFORE compute so DMA overlaps the mma stream
        const int nc = ch + STAGES - 1;
        if (nc < NCH) load_stage(nc % STAGES, nc);
        cp_commit();   // uniform group accounting

        const int s = ch % STAGES;
        const uint32_t sa  = sb + (uint32_t)s * 2 * AB_STAGE;
        const uint32_t sbB = sa + AB_STAGE;

#pragma unroll
        for (int k16 = 0; k16 < 4; k16++) {
            uint32_t afrag[4][4];
#pragma unroll
            for (int mi = 0; mi < 4; mi++) {
                int r   = wm * 64 + mi * 16 + (lane & 15);
                int c16 = k16 * 2 + (lane >> 4);
                ldsm4(afrag[mi], sa + (uint32_t)(r * 128) + ((uint32_t)(c16 ^ (r & 7)) << 4));
            }
            uint32_t bfrag[4][4];
#pragma unroll
            for (int nb = 0; nb < 4; nb++) {
                int r   = wn * 64 + nb * 16 + (lane & 7) + ((lane & 16) ? 8 : 0);
                int c16 = k16 * 2 + ((lane >> 3) & 1);
                ldsm4(bfrag[nb], sbB + (uint32_t)(r * 128) + ((uint32_t)(c16 ^ (r & 7)) << 4));
            }
#pragma unroll
            for (int mi = 0; mi < 4; mi++)
#pragma unroll
                for (int ni = 0; ni < 8; ni++)
                    mma16816(acc[mi][ni], afrag[mi], &bfrag[ni >> 1][(ni & 1) * 2]);
        }
    }

    // ---- epilogue: bias add + fp32 store ----
    const int m_base = row0 + wm * 64;
    const int n_base = col0 + wn * 64;
    const int qr = lane >> 2;
    const int qc = (lane & 3) * 2;
#pragma unroll
    for (int ni = 0; ni < 8; ni++) {
        int colg = n_base + ni * 8 + qc;
        float bx = bias[colg], by = bias[colg + 1];
#pragma unroll
        for (int mi = 0; mi < 4; mi++) {
            int rg = m_base + mi * 16 + qr;
            float2 v0 = make_float2(acc[mi][ni][0] + bx, acc[mi][ni][1] + by);
            float2 v1 = make_float2(acc[mi][ni][2] + bx, acc[mi][ni][3] + by);
            *(float2*)(C + (size_t)rg * DM + colg)       = v0;
            *(float2*)(C + (size_t)(rg + 8) * DM + colg) = v1;
        }
    }
}

// ---------------- head-mixing sparsemax attention ----------------
// One block per (a,b) token. Output written directly into the
// (B,H,A,hd)->(B,4096,1024) reshape layout with GEMM-row m2 = r*8+b,
// r = h*256 + a/16, col = (a%16)*64 + d, as fp16 hi/lo.
__global__ void __launch_bounds__(256) attn_kernel(
    const float* __restrict__ Q, const float* __restrict__ K, const float* __restrict__ V,
    __half* __restrict__ x2hi, __half* __restrict__ x2lo)
{
    __shared__ float Qs[1024];
    __shared__ float Ks[16 * 65];
    __shared__ float Vs[1024];
    __shared__ float Ps[256];

    const int m = blockIdx.x;
    const int a = m >> 3, b = m & 7;
    const int t = threadIdx.x;

    {
        float4 q4 = ((const float4*)(Q + (size_t)m * DM))[t];
        ((float4*)Qs)[t] = q4;
        float4 k4 = ((const float4*)(K + (size_t)m * DM))[t];
        int ci = t * 4;
        int krow = ci >> 6, kcol = ci & 63;
        Ks[krow * 65 + kcol]     = k4.x;
        Ks[krow * 65 + kcol + 1] = k4.y;
        Ks[krow * 65 + kcol + 2] = k4.z;
        Ks[krow * 65 + kcol + 3] = k4.w;
        float4 v4 = ((const float4*)(V + (size_t)m * DM))[t];
        ((float4*)Vs)[t] = v4;
    }
    __syncthreads();

    {
        int h = t >> 4, g = t & 15;
        float accv = 0.0f;
#pragma unroll
        for (int i = 0; i < 64; i++)
            accv = fmaf(Qs[h * 64 + i], Ks[g * 65 + i], accv);
        Ps[t] = accv * SCORE_SCALE;
    }
    __syncthreads();

    if (t < 16) {
        float z[16];
#pragma unroll
        for (int i = 0; i < 16; i++) z[i] = Ps[t * 16 + i] * inv_alpha();
#pragma unroll
        for (int k = 2; k <= 16; k <<= 1) {
#pragma unroll
            for (int j = k >> 1; j > 0; j >>= 1) {
#pragma unroll
                for (int i = 0; i < 16; i++) {
                    int l = i ^ j;
                    if (l > i) {
                        bool up = ((i & k) == 0);
                        float zi = z[i], zl = z[l];
                        bool sw = up ? (zi > zl) : (zi < zl);
                        if (sw) { z[i] = zl; z[l] = zi; }
                    }
                }
            }
        }
        float cum = 0.0f, csel = 0.0f;
        int kc = 1;
#pragma unroll
        for (int r = 1; r <= 16; r++) {
            float v = z[16 - r];
            cum += v;
            if (v * (float)r > cum - 1.0f) { kc = r; csel = cum; }
        }
        float tau = (csel - 1.0f) / (float)kc;
#pragma unroll
        for (int i = 0; i < 16; i++) {
            float p = Ps[t * 16 + i] * inv_alpha() - tau;
            Ps[t * 16 + i] = p > 0.0f ? p : 0.0f;
        }
    }
    __syncthreads();

    {
        int h = t >> 4;
        int db = (t & 15) * 4;
        float o0 = 0, o1 = 0, o2 = 0, o3 = 0;
#pragma unroll
        for (int g = 0; g < 16; g++) {
            float p = Ps[h * 16 + g];
            const float* vr = Vs + g * 64 + db;
            o0 = fmaf(p, vr[0], o0);
            o1 = fmaf(p, vr[1], o1);
            o2 = fmaf(p, vr[2], o2);
            o3 = fmaf(p, vr[3], o3);
        }
        size_t m2  = ((size_t)(h * 256 + (a >> 4))) * 8 + (size_t)b;
        int    col = (a & 15) * 64 + db;
        size_t idx = m2 * DM + col;
        float o[4] = {o0, o1, o2, o3};
#pragma unroll
        for (int j = 0; j < 4; j++) {
            __half h16 = __float2half_rn(o[j]);
            x2hi[idx + j] = h16;
            x2lo[idx + j] = __float2half_rn(o[j] - __half2float(h16));
        }
    }
}

// ---------------- launcher ----------------
extern "C" void kernel_launch(void* const* d_in, const int* in_sizes, int n_in,
                              void* d_out, int out_size)
{
    (void)in_sizes; (void)n_in; (void)out_size;

    void *pahi, *palo, *pwh, *pq, *pk, *pv, *px2h, *px2l;
    cudaGetSymbolAddress(&pahi, g_ahi);
    cudaGetSymbolAddress(&palo, g_alo);
    cudaGetSymbolAddress(&pwh,  g_wh);
    cudaGetSymbolAddress(&pq,   g_q);
    cudaGetSymbolAddress(&pk,   g_k);
    cudaGetSymbolAddress(&pv,   g_v);
    cudaGetSymbolAddress(&px2h, g_x2hi);
    cudaGetSymbolAddress(&px2l, g_x2lo);

    __half* ahi  = (__half*)pahi;
    __half* alo  = (__half*)palo;
    __half* wh   = (__half*)pwh;
    float* qbuf  = (float*)pq;
    float* kbuf  = (float*)pk;
    float* vbuf  = (float*)pv;
    __half* x2hi = (__half*)px2h;
    __half* x2lo = (__half*)px2l;

    cudaFuncSetAttribute(gemm_hmma, cudaFuncAttributeMaxDynamicSharedMemorySize, GEMM_SMEM);

    // 1) split activations (query/key/value) into fp16 hi/lo — one launch
    const int actN8 = (int)(NELEM_ACT / 8);
    split3_fp16_kernel<<<dim3(actN8 / 256, 3), 256>>>(
        (const float4*)d_in[0], (const float4*)d_in[1], (const float4*)d_in[2],
        (uint4*)ahi, (uint4*)alo, actN8);

    // 2) convert weights (Wq,Wk,Wv,Wo) to fp16 — one launch
    const int wN8 = (int)(NELEM_W / 8);
    conv4_fp16_kernel<<<dim3(wN8 / 256, 4), 256>>>(
        (const float4*)d_in[3], (const float4*)d_in[5],
        (const float4*)d_in[7], (const float4*)d_in[9],
        (uint4*)wh, wN8);

    // 3) Q/K/V projections (fp32 out, bias added); grid M-fastest
    dim3 ggrid(MROWS / BM, DM / BN);   // (256, 8)
    gemm_hmma<<<ggrid, 128, GEMM_SMEM>>>(
        ahi, alo, wh, (const float*)d_in[4], qbuf);
    gemm_hmma<<<ggrid, 128, GEMM_SMEM>>>(
        ahi + NELEM_ACT, alo + NELEM_ACT, wh + NELEM_W,
        (const float*)d_in[6], kbuf);
    gemm_hmma<<<ggrid, 128, GEMM_SMEM>>>(
        ahi + 2 * NELEM_ACT, alo + 2 * NELEM_ACT, wh + 2 * NELEM_W,
        (const float*)d_in[8], vbuf);

    // 4) sparsemax attention -> permuted X2 (hi/lo fp16)
    attn_kernel<<<MROWS, 256>>>(qbuf, kbuf, vbuf, x2hi, x2lo);

    // 5) output projection straight into d_out
    gemm_hmma<<<ggrid, 128, GEMM_SMEM>>>(
        x2hi, x2lo, wh + 3 * NELEM_W,
        (const float*)d_in[10], (float*)d_out);
}

// round 9
// speedup vs baseline: 2.6787x; 1.6434x over previous
#include <cuda_runtime.h>
#include <cuda_fp16.h>
#include <cstdint>
#include <cstddef>

// ---------------- problem constants ----------------
#define SEQA   4096
#define BATCH  8
#define DM     1024
#define MROWS  (SEQA*BATCH)          // 32768
#define NELEM_ACT ((size_t)MROWS*DM) // 33554432
#define NELEM_W   ((size_t)DM*DM)    // 1048576

static __device__ __forceinline__ float inv_alpha() { return 1.0f/1.5f; }
#define SCORE_SCALE 0.125f           // 1/sqrt(64)

// ---------------- scratch (device globals; allocation-free) ----------------
__device__ __half g_ah[3][MROWS*DM];
__device__ __half g_wh[4][DM*DM];
__device__ float g_q[MROWS*DM];
__device__ float g_k[MROWS*DM];
__device__ float g_v[MROWS*DM];
__device__ __half g_x2[MROWS*DM];

// ---------------- PTX helpers (baseline ISA only: sm_80-era) ----------------
__device__ __forceinline__ uint32_t smem_u32(const void* p) {
    uint32_t r;
    asm("{ .reg .u64 t; cvta.to.shared.u64 t, %1; cvt.u32.u64 %0, t; }"
        : "=r"(r) : "l"(p));
    return r;
}
__device__ __forceinline__ void cpasync16(uint32_t saddr, const void* g) {
    asm volatile("cp.async.cg.shared.global [%0], [%1], 16;"
                 :: "r"(saddr), "l"(g) : "memory");
}
__device__ __forceinline__ void cp_commit() {
    asm volatile("cp.async.commit_group;" ::: "memory");
}
template<int N> __device__ __forceinline__ void cp_wait() {
    asm volatile("cp.async.wait_group %0;" :: "n"(N) : "memory");
}
__device__ __forceinline__ void ldsm4(uint32_t* r, uint32_t addr) {
    asm volatile("ldmatrix.sync.aligned.m8n8.x4.shared.b16 {%0,%1,%2,%3}, [%4];"
                 : "=r"(r[0]), "=r"(r[1]), "=r"(r[2]), "=r"(r[3]) : "r"(addr));
}
__device__ __forceinline__ void mma16816(float* d, const uint32_t* a, const uint32_t* b) {
    asm volatile(
        "mma.sync.aligned.m16n8k16.row.col.f32.f16.f16.f32 "
        "{%0,%1,%2,%3}, {%4,%5,%6,%7}, {%8,%9}, {%0,%1,%2,%3};"
        : "+f"(d[0]), "+f"(d[1]), "+f"(d[2]), "+f"(d[3])
        : "r"(a[0]), "r"(a[1]), "r"(a[2]), "r"(a[3]), "r"(b[0]), "r"(b[1]));
}

// ---------------- conversion kernels: fp32 -> fp16 ----------------
// 3 activation tensors, one launch (blockIdx.y selects tensor).
__global__ void __launch_bounds__(256) conv3_fp16_kernel(
    const float4* __restrict__ x0, const float4* __restrict__ x1,
    const float4* __restrict__ x2,
    uint4* __restrict__ h, int n8)
{
    int i = blockIdx.x * blockDim.x + threadIdx.x;
    if (i >= n8) return;
    const int w = blockIdx.y;
    const float4* x = (w == 0) ? x0 : (w == 1) ? x1 : x2;
    uint4* out = h + (size_t)w * n8;

    float4 a = x[2*i];
    float4 b = x[2*i+1];
    float v[8] = {a.x, a.y, a.z, a.w, b.x, b.y, b.z, b.w};
    uint32_t hw[4];
#pragma unroll
    for (int j = 0; j < 4; j++) {
        __half2 hp = __floats2half2_rn(v[2*j], v[2*j+1]);
        hw[j] = *reinterpret_cast<uint32_t*>(&hp);
    }
    out[i] = make_uint4(hw[0], hw[1], hw[2], hw[3]);
}

// 4 weight matrices, one launch (blockIdx.y selects matrix).
__global__ void __launch_bounds__(256) conv4_fp16_kernel(
    const float4* __restrict__ w0, const float4* __restrict__ w1,
    const float4* __restrict__ w2, const float4* __restrict__ w3,
    uint4* __restrict__ h, int n8)
{
    int i = blockIdx.x * blockDim.x + threadIdx.x;
    if (i >= n8) return;
    const int w = blockIdx.y;
    const float4* x = (w == 0) ? w0 : (w == 1) ? w1 : (w == 2) ? w2 : w3;
    uint4* out = h + (size_t)w * n8;

    float4 a = x[2*i];
    float4 b = x[2*i+1];
    float v[8] = {a.x, a.y, a.z, a.w, b.x, b.y, b.z, b.w};
    uint32_t hw[4];
#pragma unroll
    for (int j = 0; j < 4; j++) {
        __half2 hp = __floats2half2_rn(v[2*j], v[2*j+1]);
        hw[j] = *reinterpret_cast<uint32_t*>(&hp);
    }
    out[i] = make_uint4(hw[0], hw[1], hw[2], hw[3]);
}

// ---------------- single-fp16 HMMA GEMM, 2 CTAs/SM ----------------
// C[32768,1024] = Ah @ Bh^T + bias (fp32 accum). K = 1024, 16 chunks of BK=64.
// CTA tile 128x128, 4 warps = 2(m) x 2(n), warp tile 64x64,
// 3-stage cp.async pipeline (96KB smem) -> 2 CTAs/SM.
// Grid is N-fastest: the 8 column-tiles of one A row-block are consecutive,
// so a wave's A slice (~10MB fp16) stays L2-resident (B is 2MB, resident).
#define BM 128
#define BN 128
#define BK 64
#define STAGES 3
#define AB_STAGE 16384                 // 128 rows x 128B (each of A and B)
#define GEMM_SMEM (STAGES * 2 * AB_STAGE)   // 98304
#define NCH 16                         // K=1024 / BK

__global__ void __launch_bounds__(128, 2) gemm_hmma(
    const __half* __restrict__ Ah, const __half* __restrict__ Bh,
    const float* __restrict__ bias, float* __restrict__ C)
{
    extern __shared__ __align__(1024) char smem[];
    const uint32_t sb = smem_u32(smem);
    const int tid  = threadIdx.x;
    const int lane = tid & 31;
    const int wid  = tid >> 5;        // 0..3
    const int wm   = wid >> 1;        // 0..1 (M 64 each)
    const int wn   = wid & 1;         // 0..1 (N 64 each)
    const int row0 = blockIdx.y * BM;
    const int col0 = blockIdx.x * BN; // N fastest-varying

    // loader lanes: 128 threads -> (row lr 0..15, 16B unit lc 0..7), 8 reps
    const int lr = tid >> 3;
    const int lc = tid & 7;

    float acc[4][8][4];
#pragma unroll
    for (int a = 0; a < 4; a++)
#pragma unroll
        for (int b = 0; b < 8; b++)
#pragma unroll
            for (int c = 0; c < 4; c++) acc[a][b][c] = 0.0f;

    auto load_stage = [&](int s, int ch) {
        const int ksub = ch * BK;
        const uint32_t sa  = sb + (uint32_t)s * 2 * AB_STAGE;
        const uint32_t sbB = sa + AB_STAGE;
#pragma unroll
        for (int rep = 0; rep < 8; rep++) {
            int r = lr + rep * 16;
            uint32_t sw = (uint32_t)(r * 128) + ((uint32_t)(lc ^ (r & 7)) << 4);
            cpasync16(sa  + sw, Ah + (size_t)(row0 + r) * DM + ksub + lc * 8);
            cpasync16(sbB + sw, Bh + (size_t)(col0 + r) * DM + ksub + lc * 8);
        }
    };

    // prologue: fill STAGES-1 stages
#pragma unroll
    for (int s = 0; s < STAGES - 1; s++) { load_stage(s, s); cp_commit(); }

    for (int ch = 0; ch < NCH; ch++) {
        cp_wait<STAGES - 2>();
        __syncthreads();

        // issue next-stage loads BEFORE compute so DMA overlaps the mma stream
        const int nc = ch + STAGES - 1;
        if (nc < NCH) load_stage(nc % STAGES, nc);
        cp_commit();   // uniform group accounting

        const int s = ch % STAGES;
        const uint32_t sa  = sb + (uint32_t)s * 2 * AB_STAGE;
        const uint32_t sbB = sa + AB_STAGE;

#pragma unroll
        for (int k16 = 0; k16 < 4; k16++) {
            uint32_t afrag[4][4];
#pragma unroll
            for (int mi = 0; mi < 4; mi++) {
                int r   = wm * 64 + mi * 16 + (lane & 15);
                int c16 = k16 * 2 + (lane >> 4);
                ldsm4(afrag[mi], sa + (uint32_t)(r * 128) + ((uint32_t)(c16 ^ (r & 7)) << 4));
            }
            uint32_t bfrag[4][4];
#pragma unroll
            for (int nb = 0; nb < 4; nb++) {
                int r   = wn * 64 + nb * 16 + (lane & 7) + ((lane & 16) ? 8 : 0);
                int c16 = k16 * 2 + ((lane >> 3) & 1);
                ldsm4(bfrag[nb], sbB + (uint32_t)(r * 128) + ((uint32_t)(c16 ^ (r & 7)) << 4));
            }
#pragma unroll
            for (int mi = 0; mi < 4; mi++)
#pragma unroll
                for (int ni = 0; ni < 8; ni++)
                    mma16816(acc[mi][ni], afrag[mi], &bfrag[ni >> 1][(ni & 1) * 2]);
        }
    }

    // ---- epilogue: bias add + fp32 store ----
    const int m_base = row0 + wm * 64;
    const int n_base = col0 + wn * 64;
    const int qr = lane >> 2;
    const int qc = (lane & 3) * 2;
#pragma unroll
    for (int ni = 0; ni < 8; ni++) {
        int colg = n_base + ni * 8 + qc;
        float bx = bias[colg], by = bias[colg + 1];
#pragma unroll
        for (int mi = 0; mi < 4; mi++) {
            int rg = m_base + mi * 16 + qr;
            float2 v0 = make_float2(acc[mi][ni][0] + bx, acc[mi][ni][1] + by);
            float2 v1 = make_float2(acc[mi][ni][2] + bx, acc[mi][ni][3] + by);
            *(float2*)(C + (size_t)rg * DM + colg)       = v0;
            *(float2*)(C + (size_t)(rg + 8) * DM + colg) = v1;
        }
    }
}

// ---------------- head-mixing sparsemax attention ----------------
// One block per (a,b) token. Output written directly into the
// (B,H,A,hd)->(B,4096,1024) reshape layout with GEMM-row m2 = r*8+b,
// r = h*256 + a/16, col = (a%16)*64 + d, as single fp16.
__global__ void __launch_bounds__(256) attn_kernel(
    const float* __restrict__ Q, const float* __restrict__ K, const float* __restrict__ V,
    __half* __restrict__ x2)
{
    __shared__ float Qs[1024];
    __shared__ float Ks[16 * 65];
    __shared__ float Vs[1024];
    __shared__ float Ps[256];

    const int m = blockIdx.x;
    const int a = m >> 3, b = m & 7;
    const int t = threadIdx.x;

    {
        float4 q4 = ((const float4*)(Q + (size_t)m * DM))[t];
        ((float4*)Qs)[t] = q4;
        float4 k4 = ((const float4*)(K + (size_t)m * DM))[t];
        int ci = t * 4;
        int krow = ci >> 6, kcol = ci & 63;
        Ks[krow * 65 + kcol]     = k4.x;
        Ks[krow * 65 + kcol + 1] = k4.y;
        Ks[krow * 65 + kcol + 2] = k4.z;
        Ks[krow * 65 + kcol + 3] = k4.w;
        float4 v4 = ((const float4*)(V + (size_t)m * DM))[t];
        ((float4*)Vs)[t] = v4;
    }
    __syncthreads();

    {
        int h = t >> 4, g = t & 15;
        float accv = 0.0f;
#pragma unroll
        for (int i = 0; i < 64; i++)
            accv = fmaf(Qs[h * 64 + i], Ks[g * 65 + i], accv);
        Ps[t] = accv * SCORE_SCALE;
    }
    __syncthreads();

    if (t < 16) {
        float z[16];
#pragma unroll
        for (int i = 0; i < 16; i++) z[i] = Ps[t * 16 + i] * inv_alpha();
#pragma unroll
        for (int k = 2; k <= 16; k <<= 1) {
#pragma unroll
            for (int j = k >> 1; j > 0; j >>= 1) {
#pragma unroll
                for (int i = 0; i < 16; i++) {
                    int l = i ^ j;
                    if (l > i) {
                        bool up = ((i & k) == 0);
                        float zi = z[i], zl = z[l];
                        bool sw = up ? (zi > zl) : (zi < zl);
                        if (sw) { z[i] = zl; z[l] = zi; }
                    }
                }
            }
        }
        float cum = 0.0f, csel = 0.0f;
        int kc = 1;
#pragma unroll
        for (int r = 1; r <= 16; r++) {
            float v = z[16 - r];
            cum += v;
            if (v * (float)r > cum - 1.0f) { kc = r; csel = cum; }
        }
        float tau = (csel - 1.0f) / (float)kc;
#pragma unroll
        for (int i = 0; i < 16; i++) {
            float p = Ps[t * 16 + i] * inv_alpha() - tau;
            Ps[t * 16 + i] = p > 0.0f ? p : 0.0f;
        }
    }
    __syncthreads();

    {
        int h = t >> 4;
        int db = (t & 15) * 4;
        float o0 = 0, o1 = 0, o2 = 0, o3 = 0;
#pragma unroll
        for (int g = 0; g < 16; g++) {
            float p = Ps[h * 16 + g];
            const float* vr = Vs + g * 64 + db;
            o0 = fmaf(p, vr[0], o0);
            o1 = fmaf(p, vr[1], o1);
            o2 = fmaf(p, vr[2], o2);
            o3 = fmaf(p, vr[3], o3);
        }
        size_t m2  = ((size_t)(h * 256 + (a >> 4))) * 8 + (size_t)b;
        int    col = (a & 15) * 64 + db;
        __half2 p0 = __floats2half2_rn(o0, o1);
        __half2 p1 = __floats2half2_rn(o2, o3);
        *(uint2*)(x2 + m2 * DM + col) =
            make_uint2(*(uint32_t*)&p0, *(uint32_t*)&p1);
    }
}

// ---------------- launcher ----------------
extern "C" void kernel_launch(void* const* d_in, const int* in_sizes, int n_in,
                              void* d_out, int out_size)
{
    (void)in_sizes; (void)n_in; (void)out_size;

    void *pah, *pwh, *pq, *pk, *pv, *px2;
    cudaGetSymbolAddress(&pah, g_ah);
    cudaGetSymbolAddress(&pwh, g_wh);
    cudaGetSymbolAddress(&pq,  g_q);
    cudaGetSymbolAddress(&pk,  g_k);
    cudaGetSymbolAddress(&pv,  g_v);
    cudaGetSymbolAddress(&px2, g_x2);

    __half* ah  = (__half*)pah;
    __half* wh  = (__half*)pwh;
    float* qbuf = (float*)pq;
    float* kbuf = (float*)pk;
    float* vbuf = (float*)pv;
    __half* x2  = (__half*)px2;

    cudaFuncSetAttribute(gemm_hmma, cudaFuncAttributeMaxDynamicSharedMemorySize, GEMM_SMEM);

    // 1) convert activations (query/key/value) to fp16 — one launch
    const int actN8 = (int)(NELEM_ACT / 8);
    conv3_fp16_kernel<<<dim3(actN8 / 256, 3), 256>>>(
        (const float4*)d_in[0], (const float4*)d_in[1], (const float4*)d_in[2],
        (uint4*)ah, actN8);

    // 2) convert weights (Wq,Wk,Wv,Wo) to fp16 — one launch
    const int wN8 = (int)(NELEM_W / 8);
    conv4_fp16_kernel<<<dim3(wN8 / 256, 4), 256>>>(
        (const float4*)d_in[3], (const float4*)d_in[5],
        (const float4*)d_in[7], (const float4*)d_in[9],
        (uint4*)wh, wN8);

    // 3) Q/K/V projections (fp32 out, bias added); grid N-fastest for A reuse
    dim3 ggrid(DM / BN, MROWS / BM);   // (8, 256)
    gemm_hmma<<<ggrid, 128, GEMM_SMEM>>>(
        ah, wh, (const float*)d_in[4], qbuf);
    gemm_hmma<<<ggrid, 128, GEMM_SMEM>>>(
        ah + NELEM_ACT, wh + NELEM_W, (const float*)d_in[6], kbuf);
    gemm_hmma<<<ggrid, 128, GEMM_SMEM>>>(
        ah + 2 * NELEM_ACT, wh + 2 * NELEM_W, (const float*)d_in[8], vbuf);

    // 4) sparsemax attention -> permuted X2 (fp16)
    attn_kernel<<<MROWS, 256>>>(qbuf, kbuf, vbuf, x2);

    // 5) output projection straight into d_out
    gemm_hmma<<<ggrid, 128, GEMM_SMEM>>>(
        x2, wh + 3 * NELEM_W, (const float*)d_in[10], (float*)d_out);
}

// round 10
// speedup vs baseline: 2.7196x; 1.0153x over previous
#include <cuda_runtime.h>
#include <cuda_fp16.h>
#include <cstdint>
#include <cstddef>

// ---------------- problem constants ----------------
#define SEQA   4096
#define BATCH  8
#define DM     1024
#define MROWS  (SEQA*BATCH)          // 32768
#define NELEM_ACT ((size_t)MROWS*DM) // 33554432
#define NELEM_W   ((size_t)DM*DM)    // 1048576

static __device__ __forceinline__ float inv_alpha() { return 1.0f/1.5f; }
#define SCORE_SCALE 0.125f           // 1/sqrt(64)

// ---------------- scratch (device globals; allocation-free) ----------------
__device__ __half g_ah[3][MROWS*DM];
__device__ __half g_wh[4][DM*DM];
__device__ __half g_q[MROWS*DM];
__device__ __half g_k[MROWS*DM];
__device__ __half g_v[MROWS*DM];
__device__ __half g_x2[MROWS*DM];

// ---------------- PTX helpers (baseline ISA only: sm_80-era) ----------------
__device__ __forceinline__ uint32_t smem_u32(const void* p) {
    uint32_t r;
    asm("{ .reg .u64 t; cvta.to.shared.u64 t, %1; cvt.u32.u64 %0, t; }"
        : "=r"(r) : "l"(p));
    return r;
}
__device__ __forceinline__ void cpasync16(uint32_t saddr, const void* g) {
    asm volatile("cp.async.cg.shared.global [%0], [%1], 16;"
                 :: "r"(saddr), "l"(g) : "memory");
}
__device__ __forceinline__ void cp_commit() {
    asm volatile("cp.async.commit_group;" ::: "memory");
}
template<int N> __device__ __forceinline__ void cp_wait() {
    asm volatile("cp.async.wait_group %0;" :: "n"(N) : "memory");
}
__device__ __forceinline__ void ldsm4(uint32_t* r, uint32_t addr) {
    asm volatile("ldmatrix.sync.aligned.m8n8.x4.shared.b16 {%0,%1,%2,%3}, [%4];"
                 : "=r"(r[0]), "=r"(r[1]), "=r"(r[2]), "=r"(r[3]) : "r"(addr));
}
__device__ __forceinline__ void mma16816(float* d, const uint32_t* a, const uint32_t* b) {
    asm volatile(
        "mma.sync.aligned.m16n8k16.row.col.f32.f16.f16.f32 "
        "{%0,%1,%2,%3}, {%4,%5,%6,%7}, {%8,%9}, {%0,%1,%2,%3};"
        : "+f"(d[0]), "+f"(d[1]), "+f"(d[2]), "+f"(d[3])
        : "r"(a[0]), "r"(a[1]), "r"(a[2]), "r"(a[3]), "r"(b[0]), "r"(b[1]));
}

// ---------------- conversion kernels: fp32 -> fp16 ----------------
__global__ void __launch_bounds__(256) conv3_fp16_kernel(
    const float4* __restrict__ x0, const float4* __restrict__ x1,
    const float4* __restrict__ x2,
    uint4* __restrict__ h, int n8)
{
    int i = blockIdx.x * blockDim.x + threadIdx.x;
    if (i >= n8) return;
    const int w = blockIdx.y;
    const float4* x = (w == 0) ? x0 : (w == 1) ? x1 : x2;
    uint4* out = h + (size_t)w * n8;

    float4 a = x[2*i];
    float4 b = x[2*i+1];
    float v[8] = {a.x, a.y, a.z, a.w, b.x, b.y, b.z, b.w};
    uint32_t hw[4];
#pragma unroll
    for (int j = 0; j < 4; j++) {
        __half2 hp = __floats2half2_rn(v[2*j], v[2*j+1]);
        hw[j] = *reinterpret_cast<uint32_t*>(&hp);
    }
    out[i] = make_uint4(hw[0], hw[1], hw[2], hw[3]);
}

__global__ void __launch_bounds__(256) conv4_fp16_kernel(
    const float4* __restrict__ w0, const float4* __restrict__ w1,
    const float4* __restrict__ w2, const float4* __restrict__ w3,
    uint4* __restrict__ h, int n8)
{
    int i = blockIdx.x * blockDim.x + threadIdx.x;
    if (i >= n8) return;
    const int w = blockIdx.y;
    const float4* x = (w == 0) ? w0 : (w == 1) ? w1 : (w == 2) ? w2 : w3;
    uint4* out = h + (size_t)w * n8;

    float4 a = x[2*i];
    float4 b = x[2*i+1];
    float v[8] = {a.x, a.y, a.z, a.w, b.x, b.y, b.z, b.w};
    uint32_t hw[4];
#pragma unroll
    for (int j = 0; j < 4; j++) {
        __half2 hp = __floats2half2_rn(v[2*j], v[2*j+1]);
        hw[j] = *reinterpret_cast<uint32_t*>(&hp);
    }
    out[i] = make_uint4(hw[0], hw[1], hw[2], hw[3]);
}

// ---------------- single-fp16 HMMA GEMM, 2 CTAs/SM ----------------
// C[32768,1024] = Ah @ Bh^T + bias (fp32 accum). K = 1024, 16 chunks of BK=64.
// CTA tile 128x128, 4 warps = 2(m) x 2(n), warp tile 64x64,
// 3-stage cp.async pipeline (96KB smem) -> 2 CTAs/SM.
// Grid is N-fastest so a wave's A slice stays L2-resident.
// HALF_OUT=1 stores C as fp16 (Q/K/V path), =0 stores fp32 (final output).
#define BM 128
#define BN 128
#define BK 64
#define STAGES 3
#define AB_STAGE 16384                 // 128 rows x 128B (each of A and B)
#define GEMM_SMEM (STAGES * 2 * AB_STAGE)   // 98304
#define NCH 16                         // K=1024 / BK

template<int HALF_OUT>
__global__ void __launch_bounds__(128, 2) gemm_hmma(
    const __half* __restrict__ Ah, const __half* __restrict__ Bh,
    const float* __restrict__ bias, void* __restrict__ Cv)
{
    extern __shared__ __align__(1024) char smem[];
    const uint32_t sb = smem_u32(smem);
    const int tid  = threadIdx.x;
    const int lane = tid & 31;
    const int wid  = tid >> 5;        // 0..3
    const int wm   = wid >> 1;        // 0..1 (M 64 each)
    const int wn   = wid & 1;         // 0..1 (N 64 each)
    const int row0 = blockIdx.y * BM;
    const int col0 = blockIdx.x * BN; // N fastest-varying

    const int lr = tid >> 3;
    const int lc = tid & 7;

    float acc[4][8][4];
#pragma unroll
    for (int a = 0; a < 4; a++)
#pragma unroll
        for (int b = 0; b < 8; b++)
#pragma unroll
            for (int c = 0; c < 4; c++) acc[a][b][c] = 0.0f;

    auto load_stage = [&](int s, int ch) {
        const int ksub = ch * BK;
        const uint32_t sa  = sb + (uint32_t)s * 2 * AB_STAGE;
        const uint32_t sbB = sa + AB_STAGE;
#pragma unroll
        for (int rep = 0; rep < 8; rep++) {
            int r = lr + rep * 16;
            uint32_t sw = (uint32_t)(r * 128) + ((uint32_t)(lc ^ (r & 7)) << 4);
            cpasync16(sa  + sw, Ah + (size_t)(row0 + r) * DM + ksub + lc * 8);
            cpasync16(sbB + sw, Bh + (size_t)(col0 + r) * DM + ksub + lc * 8);
        }
    };

#pragma unroll
    for (int s = 0; s < STAGES - 1; s++) { load_stage(s, s); cp_commit(); }

    for (int ch = 0; ch < NCH; ch++) {
        cp_wait<STAGES - 2>();
        __syncthreads();

        const int nc = ch + STAGES - 1;
        if (nc < NCH) load_stage(nc % STAGES, nc);
        cp_commit();

        const int s = ch % STAGES;
        const uint32_t sa  = sb + (uint32_t)s * 2 * AB_STAGE;
        const uint32_t sbB = sa + AB_STAGE;

#pragma unroll
        for (int k16 = 0; k16 < 4; k16++) {
            uint32_t afrag[4][4];
#pragma unroll
            for (int mi = 0; mi < 4; mi++) {
                int r   = wm * 64 + mi * 16 + (lane & 15);
                int c16 = k16 * 2 + (lane >> 4);
                ldsm4(afrag[mi], sa + (uint32_t)(r * 128) + ((uint32_t)(c16 ^ (r & 7)) << 4));
            }
            uint32_t bfrag[4][4];
#pragma unroll
            for (int nb = 0; nb < 4; nb++) {
                int r   = wn * 64 + nb * 16 + (lane & 7) + ((lane & 16) ? 8 : 0);
                int c16 = k16 * 2 + ((lane >> 3) & 1);
                ldsm4(bfrag[nb], sbB + (uint32_t)(r * 128) + ((uint32_t)(c16 ^ (r & 7)) << 4));
            }
#pragma unroll
            for (int mi = 0; mi < 4; mi++)
#pragma unroll
                for (int ni = 0; ni < 8; ni++)
                    mma16816(acc[mi][ni], afrag[mi], &bfrag[ni >> 1][(ni & 1) * 2]);
        }
    }

    // ---- epilogue: bias add + store (fp16 or fp32) ----
    const int m_base = row0 + wm * 64;
    const int n_base = col0 + wn * 64;
    const int qr = lane >> 2;
    const int qc = (lane & 3) * 2;
#pragma unroll
    for (int ni = 0; ni < 8; ni++) {
        int colg = n_base + ni * 8 + qc;
        float bx = bias[colg], by = bias[colg + 1];
#pragma unroll
        for (int mi = 0; mi < 4; mi++) {
            int rg = m_base + mi * 16 + qr;
            float v00 = acc[mi][ni][0] + bx, v01 = acc[mi][ni][1] + by;
            float v10 = acc[mi][ni][2] + bx, v11 = acc[mi][ni][3] + by;
            if (HALF_OUT) {
                __half* C = (__half*)Cv;
                __half2 h0 = __floats2half2_rn(v00, v01);
                __half2 h1 = __floats2half2_rn(v10, v11);
                *(uint32_t*)(C + (size_t)rg * DM + colg)       = *(uint32_t*)&h0;
                *(uint32_t*)(C + (size_t)(rg + 8) * DM + colg) = *(uint32_t*)&h1;
            } else {
                float* C = (float*)Cv;
                *(float2*)(C + (size_t)rg * DM + colg)       = make_float2(v00, v01);
                *(float2*)(C + (size_t)(rg + 8) * DM + colg) = make_float2(v10, v11);
            }
        }
    }
}

// ---------------- head-mixing sparsemax attention (fp16 in, fp16 out) -------
// One block per (a,b) token. Output written directly into the
// (B,H,A,hd)->(B,4096,1024) reshape layout with GEMM-row m2 = r*8+b,
// r = h*256 + a/16, col = (a%16)*64 + d.
__global__ void __launch_bounds__(256) attn_kernel(
    const __half* __restrict__ Q, const __half* __restrict__ K,
    const __half* __restrict__ V, __half* __restrict__ x2)
{
    __shared__ float Qs[1024];
    __shared__ float Ks[16 * 65];   // padded stride 65
    __shared__ float Vs[1024];
    __shared__ float Ps[256];

    const int m = blockIdx.x;
    const int a = m >> 3, b = m & 7;
    const int t = threadIdx.x;

    // load rows: 256 threads x 4 halves (uint2) = 1024 elements each
    {
        uint2 qu = ((const uint2*)(Q + (size_t)m * DM))[t];
        __half2 q0 = *(__half2*)&qu.x, q1 = *(__half2*)&qu.y;
        int ci = t * 4;
        Qs[ci]     = __low2float(q0);
        Qs[ci + 1] = __high2float(q0);
        Qs[ci + 2] = __low2float(q1);
        Qs[ci + 3] = __high2float(q1);

        uint2 ku = ((const uint2*)(K + (size_t)m * DM))[t];
        __half2 k0 = *(__half2*)&ku.x, k1 = *(__half2*)&ku.y;
        int krow = ci >> 6, kcol = ci & 63;
        Ks[krow * 65 + kcol]     = __low2float(k0);
        Ks[krow * 65 + kcol + 1] = __high2float(k0);
        Ks[krow * 65 + kcol + 2] = __low2float(k1);
        Ks[krow * 65 + kcol + 3] = __high2float(k1);

        uint2 vu = ((const uint2*)(V + (size_t)m * DM))[t];
        __half2 v0 = *(__half2*)&vu.x, v1 = *(__half2*)&vu.y;
        Vs[ci]     = __low2float(v0);
        Vs[ci + 1] = __high2float(v0);
        Vs[ci + 2] = __low2float(v1);
        Vs[ci + 3] = __high2float(v1);
    }
    __syncthreads();

    // scores: thread t -> (h = t/16, g = t%16)
    {
        int h = t >> 4, g = t & 15;
        float accv = 0.0f;
#pragma unroll
        for (int i = 0; i < 64; i++)
            accv = fmaf(Qs[h * 64 + i], Ks[g * 65 + i], accv);
        Ps[t] = accv * SCORE_SCALE;
    }
    __syncthreads();

    // sparsemax over the 16 scores of head t (threads 0..15)
    if (t < 16) {
        float z[16];
#pragma unroll
        for (int i = 0; i < 16; i++) z[i] = Ps[t * 16 + i] * inv_alpha();
#pragma unroll
        for (int k = 2; k <= 16; k <<= 1) {
#pragma unroll
            for (int j = k >> 1; j > 0; j >>= 1) {
#pragma unroll
                for (int i = 0; i < 16; i++) {
                    int l = i ^ j;
                    if (l > i) {
                        bool up = ((i & k) == 0);
                        float zi = z[i], zl = z[l];
                        bool sw = up ? (zi > zl) : (zi < zl);
                        if (sw) { z[i] = zl; z[l] = zi; }
                    }
                }
            }
        }
        float cum = 0.0f, csel = 0.0f;
        int kc = 1;
#pragma unroll
        for (int r = 1; r <= 16; r++) {
            float v = z[16 - r];
            cum += v;
            if (v * (float)r > cum - 1.0f) { kc = r; csel = cum; }
        }
        float tau = (csel - 1.0f) / (float)kc;
#pragma unroll
        for (int i = 0; i < 16; i++) {
            float p = Ps[t * 16 + i] * inv_alpha() - tau;
            Ps[t * 16 + i] = p > 0.0f ? p : 0.0f;
        }
    }
    __syncthreads();

    // AV: thread t -> (h = t/16, d-base = (t%16)*4)
    {
        int h = t >> 4;
        int db = (t & 15) * 4;
        float o0 = 0, o1 = 0, o2 = 0, o3 = 0;
#pragma unroll
        for (int g = 0; g < 16; g++) {
            float p = Ps[h * 16 + g];
            const float* vr = Vs + g * 64 + db;
            o0 = fmaf(p, vr[0], o0);
            o1 = fmaf(p, vr[1], o1);
            o2 = fmaf(p, vr[2], o2);
            o3 = fmaf(p, vr[3], o3);
        }
        size_t m2  = ((size_t)(h * 256 + (a >> 4))) * 8 + (size_t)b;
        int    col = (a & 15) * 64 + db;
        __half2 p0 = __floats2half2_rn(o0, o1);
        __half2 p1 = __floats2half2_rn(o2, o3);
        *(uint2*)(x2 + m2 * DM + col) =
            make_uint2(*(uint32_t*)&p0, *(uint32_t*)&p1);
    }
}

// ---------------- launcher ----------------
extern "C" void kernel_launch(void* const* d_in, const int* in_sizes, int n_in,
                              void* d_out, int out_size)
{
    (void)in_sizes; (void)n_in; (void)out_size;

    void *pah, *pwh, *pq, *pk, *pv, *px2;
    cudaGetSymbolAddress(&pah, g_ah);
    cudaGetSymbolAddress(&pwh, g_wh);
    cudaGetSymbolAddress(&pq,  g_q);
    cudaGetSymbolAddress(&pk,  g_k);
    cudaGetSymbolAddress(&pv,  g_v);
    cudaGetSymbolAddress(&px2, g_x2);

    __half* ah   = (__half*)pah;
    __half* wh   = (__half*)pwh;
    __half* qbuf = (__half*)pq;
    __half* kbuf = (__half*)pk;
    __half* vbuf = (__half*)pv;
    __half* x2   = (__half*)px2;

    cudaFuncSetAttribute(gemm_hmma<0>, cudaFuncAttributeMaxDynamicSharedMemorySize, GEMM_SMEM);
    cudaFuncSetAttribute(gemm_hmma<1>, cudaFuncAttributeMaxDynamicSharedMemorySize, GEMM_SMEM);

    // 1) convert activations (query/key/value) to fp16 — one launch
    const int actN8 = (int)(NELEM_ACT / 8);
    conv3_fp16_kernel<<<dim3(actN8 / 256, 3), 256>>>(
        (const float4*)d_in[0], (const float4*)d_in[1], (const float4*)d_in[2],
        (uint4*)ah, actN8);

    // 2) convert weights (Wq,Wk,Wv,Wo) to fp16 — one launch
    const int wN8 = (int)(NELEM_W / 8);
    conv4_fp16_kernel<<<dim3(wN8 / 256, 4), 256>>>(
        (const float4*)d_in[3], (const float4*)d_in[5],
        (const float4*)d_in[7], (const float4*)d_in[9],
        (uint4*)wh, wN8);

    // 3) Q/K/V projections -> fp16 outputs; grid N-fastest for A reuse
    dim3 ggrid(DM / BN, MROWS / BM);   // (8, 256)
    gemm_hmma<1><<<ggrid, 128, GEMM_SMEM>>>(
        ah, wh, (const float*)d_in[4], qbuf);
    gemm_hmma<1><<<ggrid, 128, GEMM_SMEM>>>(
        ah + NELEM_ACT, wh + NELEM_W, (const float*)d_in[6], kbuf);
    gemm_hmma<1><<<ggrid, 128, GEMM_SMEM>>>(
        ah + 2 * NELEM_ACT, wh + 2 * NELEM_W, (const float*)d_in[8], vbuf);

    // 4) sparsemax attention (fp16 in) -> permuted X2 (fp16)
    attn_kernel<<<MROWS, 256>>>(qbuf, kbuf, vbuf, x2);

    // 5) output projection straight into d_out (fp32)
    gemm_hmma<0><<<ggrid, 128, GEMM_SMEM>>>(
        x2, wh + 3 * NELEM_W, (const float*)d_in[10], (float*)d_out);
}

// round 11
// speedup vs baseline: 2.7747x; 1.0203x over previous
#include <cuda_runtime.h>
#include <cuda_fp16.h>
#include <cstdint>
#include <cstddef>

// ---------------- problem constants ----------------
#define SEQA   4096
#define BATCH  8
#define DM     1024
#define MROWS  (SEQA*BATCH)          // 32768
#define NELEM_ACT ((size_t)MROWS*DM) // 33554432
#define NELEM_W   ((size_t)DM*DM)    // 1048576

static __device__ __forceinline__ float inv_alpha() { return 1.0f/1.5f; }
#define SCORE_SCALE 0.125f           // 1/sqrt(64)

// ---------------- scratch (device globals; allocation-free) ----------------
__device__ __half g_ah[3][MROWS*DM];
__device__ __half g_wh[4][DM*DM];
__device__ __half g_q[MROWS*DM];
__device__ __half g_k[MROWS*DM];
__device__ __half g_v[MROWS*DM];
__device__ __half g_x2[MROWS*DM];

// ---------------- PTX helpers (baseline ISA only: sm_80-era) ----------------
__device__ __forceinline__ uint32_t smem_u32(const void* p) {
    uint32_t r;
    asm("{ .reg .u64 t; cvta.to.shared.u64 t, %1; cvt.u32.u64 %0, t; }"
        : "=r"(r) : "l"(p));
    return r;
}
__device__ __forceinline__ void cpasync16(uint32_t saddr, const void* g) {
    asm volatile("cp.async.cg.shared.global [%0], [%1], 16;"
                 :: "r"(saddr), "l"(g) : "memory");
}
__device__ __forceinline__ void cp_commit() {
    asm volatile("cp.async.commit_group;" ::: "memory");
}
template<int N> __device__ __forceinline__ void cp_wait() {
    asm volatile("cp.async.wait_group %0;" :: "n"(N) : "memory");
}
__device__ __forceinline__ void ldsm4(uint32_t* r, uint32_t addr) {
    asm volatile("ldmatrix.sync.aligned.m8n8.x4.shared.b16 {%0,%1,%2,%3}, [%4];"
                 : "=r"(r[0]), "=r"(r[1]), "=r"(r[2]), "=r"(r[3]) : "r"(addr));
}
__device__ __forceinline__ void mma16816(float* d, const uint32_t* a, const uint32_t* b) {
    asm volatile(
        "mma.sync.aligned.m16n8k16.row.col.f32.f16.f16.f32 "
        "{%0,%1,%2,%3}, {%4,%5,%6,%7}, {%8,%9}, {%0,%1,%2,%3};"
        : "+f"(d[0]), "+f"(d[1]), "+f"(d[2]), "+f"(d[3])
        : "r"(a[0]), "r"(a[1]), "r"(a[2]), "r"(a[3]), "r"(b[0]), "r"(b[1]));
}

// ---------------- conversion kernels: fp32 -> fp16 ----------------
// 3 activation tensors, one launch; 2 uint4 outputs per thread.
__global__ void __launch_bounds__(256) conv3_fp16_kernel(
    const float4* __restrict__ x0, const float4* __restrict__ x1,
    const float4* __restrict__ x2,
    uint4* __restrict__ h, int n8)
{
    int i0 = (blockIdx.x * blockDim.x + threadIdx.x) * 2;
    if (i0 >= n8) return;
    const int w = blockIdx.y;
    const float4* x = (w == 0) ? x0 : (w == 1) ? x1 : x2;
    uint4* out = h + (size_t)w * n8;

#pragma unroll
    for (int e = 0; e < 2; e++) {
        int i = i0 + e;
        float4 a = x[2*i];
        float4 b = x[2*i+1];
        float v[8] = {a.x, a.y, a.z, a.w, b.x, b.y, b.z, b.w};
        uint32_t hw[4];
#pragma unroll
        for (int j = 0; j < 4; j++) {
            __half2 hp = __floats2half2_rn(v[2*j], v[2*j+1]);
            hw[j] = *reinterpret_cast<uint32_t*>(&hp);
        }
        out[i] = make_uint4(hw[0], hw[1], hw[2], hw[3]);
    }
}

// 4 weight matrices, one launch (blockIdx.y selects matrix).
__global__ void __launch_bounds__(256) conv4_fp16_kernel(
    const float4* __restrict__ w0, const float4* __restrict__ w1,
    const float4* __restrict__ w2, const float4* __restrict__ w3,
    uint4* __restrict__ h, int n8)
{
    int i = blockIdx.x * blockDim.x + threadIdx.x;
    if (i >= n8) return;
    const int w = blockIdx.y;
    const float4* x = (w == 0) ? w0 : (w == 1) ? w1 : (w == 2) ? w2 : w3;
    uint4* out = h + (size_t)w * n8;

    float4 a = x[2*i];
    float4 b = x[2*i+1];
    float v[8] = {a.x, a.y, a.z, a.w, b.x, b.y, b.z, b.w};
    uint32_t hw[4];
#pragma unroll
    for (int j = 0; j < 4; j++) {
        __half2 hp = __floats2half2_rn(v[2*j], v[2*j+1]);
        hw[j] = *reinterpret_cast<uint32_t*>(&hp);
    }
    out[i] = make_uint4(hw[0], hw[1], hw[2], hw[3]);
}

// ---------------- single-fp16 HMMA GEMM core (shared by both launchers) -----
#define BM 128
#define BN 128
#define BK 64
#define STAGES 3
#define AB_STAGE 16384                 // 128 rows x 128B (each of A and B)
#define GEMM_SMEM (STAGES * 2 * AB_STAGE)   // 98304
#define NCH 16                         // K=1024 / BK

template<int HALF_OUT>
__device__ __forceinline__ void gemm_core(
    const __half* __restrict__ Ah, const __half* __restrict__ Bh,
    const float* __restrict__ bias, void* __restrict__ Cv,
    char* smem, int bx, int by)
{
    const uint32_t sb = smem_u32(smem);
    const int tid  = threadIdx.x;
    const int lane = tid & 31;
    const int wid  = tid >> 5;        // 0..3
    const int wm   = wid >> 1;        // 0..1 (M 64 each)
    const int wn   = wid & 1;         // 0..1 (N 64 each)
    const int row0 = by * BM;
    const int col0 = bx * BN;         // N fastest-varying

    const int lr = tid >> 3;
    const int lc = tid & 7;

    float acc[4][8][4];
#pragma unroll
    for (int a = 0; a < 4; a++)
#pragma unroll
        for (int b = 0; b < 8; b++)
#pragma unroll
            for (int c = 0; c < 4; c++) acc[a][b][c] = 0.0f;

    auto load_stage = [&](int s, int ch) {
        const int ksub = ch * BK;
        const uint32_t sa  = sb + (uint32_t)s * 2 * AB_STAGE;
        const uint32_t sbB = sa + AB_STAGE;
#pragma unroll
        for (int rep = 0; rep < 8; rep++) {
            int r = lr + rep * 16;
            uint32_t sw = (uint32_t)(r * 128) + ((uint32_t)(lc ^ (r & 7)) << 4);
            cpasync16(sa  + sw, Ah + (size_t)(row0 + r) * DM + ksub + lc * 8);
            cpasync16(sbB + sw, Bh + (size_t)(col0 + r) * DM + ksub + lc * 8);
        }
    };

#pragma unroll
    for (int s = 0; s < STAGES - 1; s++) { load_stage(s, s); cp_commit(); }

    for (int ch = 0; ch < NCH; ch++) {
        cp_wait<STAGES - 2>();
        __syncthreads();

        const int nc = ch + STAGES - 1;
        if (nc < NCH) load_stage(nc % STAGES, nc);
        cp_commit();

        const int s = ch % STAGES;
        const uint32_t sa  = sb + (uint32_t)s * 2 * AB_STAGE;
        const uint32_t sbB = sa + AB_STAGE;

#pragma unroll
        for (int k16 = 0; k16 < 4; k16++) {
            uint32_t afrag[4][4];
#pragma unroll
            for (int mi = 0; mi < 4; mi++) {
                int r   = wm * 64 + mi * 16 + (lane & 15);
                int c16 = k16 * 2 + (lane >> 4);
                ldsm4(afrag[mi], sa + (uint32_t)(r * 128) + ((uint32_t)(c16 ^ (r & 7)) << 4));
            }
            uint32_t bfrag[4][4];
#pragma unroll
            for (int nb = 0; nb < 4; nb++) {
                int r   = wn * 64 + nb * 16 + (lane & 7) + ((lane & 16) ? 8 : 0);
                int c16 = k16 * 2 + ((lane >> 3) & 1);
                ldsm4(bfrag[nb], sbB + (uint32_t)(r * 128) + ((uint32_t)(c16 ^ (r & 7)) << 4));
            }
#pragma unroll
            for (int mi = 0; mi < 4; mi++)
#pragma unroll
                for (int ni = 0; ni < 8; ni++)
                    mma16816(acc[mi][ni], afrag[mi], &bfrag[ni >> 1][(ni & 1) * 2]);
        }
    }

    // ---- epilogue: bias add + store (fp16 or fp32) ----
    const int m_base = row0 + wm * 64;
    const int n_base = col0 + wn * 64;
    const int qr = lane >> 2;
    const int qc = (lane & 3) * 2;
#pragma unroll
    for (int ni = 0; ni < 8; ni++) {
        int colg = n_base + ni * 8 + qc;
        float bx2 = bias[colg], by2 = bias[colg + 1];
#pragma unroll
        for (int mi = 0; mi < 4; mi++) {
            int rg = m_base + mi * 16 + qr;
            float v00 = acc[mi][ni][0] + bx2, v01 = acc[mi][ni][1] + by2;
            float v10 = acc[mi][ni][2] + bx2, v11 = acc[mi][ni][3] + by2;
            if (HALF_OUT) {
                __half* C = (__half*)Cv;
                __half2 h0 = __floats2half2_rn(v00, v01);
                __half2 h1 = __floats2half2_rn(v10, v11);
                *(uint32_t*)(C + (size_t)rg * DM + colg)       = *(uint32_t*)&h0;
                *(uint32_t*)(C + (size_t)(rg + 8) * DM + colg) = *(uint32_t*)&h1;
            } else {
                float* C = (float*)Cv;
                *(float2*)(C + (size_t)rg * DM + colg)       = make_float2(v00, v01);
                *(float2*)(C + (size_t)(rg + 8) * DM + colg) = make_float2(v10, v11);
            }
        }
    }
}

// merged Q/K/V projection: grid.z = 3 selects (A, bias, C); one tail not three
__global__ void __launch_bounds__(128, 2) gemm_qkv(
    const __half* __restrict__ Ah0, const __half* __restrict__ Wh,
    const float* __restrict__ bq, const float* __restrict__ bk,
    const float* __restrict__ bv,
    __half* __restrict__ Cq, __half* __restrict__ Ck, __half* __restrict__ Cv2)
{
    extern __shared__ __align__(1024) char smem[];
    const int z = blockIdx.z;
    const __half* Ah = Ah0 + (size_t)z * NELEM_ACT;
    const __half* Bh = Wh  + (size_t)z * NELEM_W;
    const float* bias = (z == 0) ? bq : (z == 1) ? bk : bv;
    __half* C = (z == 0) ? Cq : (z == 1) ? Ck : Cv2;
    gemm_core<1>(Ah, Bh, bias, C, smem, blockIdx.x, blockIdx.y);
}

// final output projection (fp32 out)
__global__ void __launch_bounds__(128, 2) gemm_out(
    const __half* __restrict__ Ah, const __half* __restrict__ Bh,
    const float* __restrict__ bias, float* __restrict__ C)
{
    extern __shared__ __align__(1024) char smem[];
    gemm_core<0>(Ah, Bh, bias, C, smem, blockIdx.x, blockIdx.y);
}

// ---------------- head-mixing sparsemax attention (fp16 in, fp16 out) -------
// One block per (a,b) token. Output written directly into the
// (B,H,A,hd)->(B,4096,1024) reshape layout with GEMM-row m2 = r*8+b,
// r = h*256 + a/16, col = (a%16)*64 + d.
__global__ void __launch_bounds__(256) attn_kernel(
    const __half* __restrict__ Q, const __half* __restrict__ K,
    const __half* __restrict__ V, __half* __restrict__ x2)
{
    __shared__ float Qs[1024];
    __shared__ float Ks[16 * 65];   // padded stride 65
    __shared__ float Vs[1024];
    __shared__ float Ps[256];

    const int m = blockIdx.x;
    const int a = m >> 3, b = m & 7;
    const int t = threadIdx.x;

    {
        uint2 qu = ((const uint2*)(Q + (size_t)m * DM))[t];
        __half2 q0 = *(__half2*)&qu.x, q1 = *(__half2*)&qu.y;
        int ci = t * 4;
        Qs[ci]     = __low2float(q0);
        Qs[ci + 1] = __high2float(q0);
        Qs[ci + 2] = __low2float(q1);
        Qs[ci + 3] = __high2float(q1);

        uint2 ku = ((const uint2*)(K + (size_t)m * DM))[t];
        __half2 k0 = *(__half2*)&ku.x, k1 = *(__half2*)&ku.y;
        int krow = ci >> 6, kcol = ci & 63;
        Ks[krow * 65 + kcol]     = __low2float(k0);
        Ks[krow * 65 + kcol + 1] = __high2float(k0);
        Ks[krow * 65 + kcol + 2] = __low2float(k1);
        Ks[krow * 65 + kcol + 3] = __high2float(k1);

        uint2 vu = ((const uint2*)(V + (size_t)m * DM))[t];
        __half2 v0 = *(__half2*)&vu.x, v1 = *(__half2*)&vu.y;
        Vs[ci]     = __low2float(v0);
        Vs[ci + 1] = __high2float(v0);
        Vs[ci + 2] = __low2float(v1);
        Vs[ci + 3] = __high2float(v1);
    }
    __syncthreads();

    {
        int h = t >> 4, g = t & 15;
        float accv = 0.0f;
#pragma unroll
        for (int i = 0; i < 64; i++)
            accv = fmaf(Qs[h * 64 + i], Ks[g * 65 + i], accv);
        Ps[t] = accv * SCORE_SCALE;
    }
    __syncthreads();

    if (t < 16) {
        float z[16];
#pragma unroll
        for (int i = 0; i < 16; i++) z[i] = Ps[t * 16 + i] * inv_alpha();
#pragma unroll
        for (int k = 2; k <= 16; k <<= 1) {
#pragma unroll
            for (int j = k >> 1; j > 0; j >>= 1) {
#pragma unroll
                for (int i = 0; i < 16; i++) {
                    int l = i ^ j;
                    if (l > i) {
                        bool up = ((i & k) == 0);
                        float zi = z[i], zl = z[l];
                        bool sw = up ? (zi > zl) : (zi < zl);
                        if (sw) { z[i] = zl; z[l] = zi; }
                    }
                }
            }
        }
        float cum = 0.0f, csel = 0.0f;
        int kc = 1;
#pragma unroll
        for (int r = 1; r <= 16; r++) {
            float v = z[16 - r];
            cum += v;
            if (v * (float)r > cum - 1.0f) { kc = r; csel = cum; }
        }
        float tau = (csel - 1.0f) / (float)kc;
#pragma unroll
        for (int i = 0; i < 16; i++) {
            float p = Ps[t * 16 + i] * inv_alpha() - tau;
            Ps[t * 16 + i] = p > 0.0f ? p : 0.0f;
        }
    }
    __syncthreads();

    {
        int h = t >> 4;
        int db = (t & 15) * 4;
        float o0 = 0, o1 = 0, o2 = 0, o3 = 0;
#pragma unroll
        for (int g = 0; g < 16; g++) {
            float p = Ps[h * 16 + g];
            const float* vr = Vs + g * 64 + db;
            o0 = fmaf(p, vr[0], o0);
            o1 = fmaf(p, vr[1], o1);
            o2 = fmaf(p, vr[2], o2);
            o3 = fmaf(p, vr[3], o3);
        }
        size_t m2  = ((size_t)(h * 256 + (a >> 4))) * 8 + (size_t)b;
        int    col = (a & 15) * 64 + db;
        __half2 p0 = __floats2half2_rn(o0, o1);
        __half2 p1 = __floats2half2_rn(o2, o3);
        *(uint2*)(x2 + m2 * DM + col) =
            make_uint2(*(uint32_t*)&p0, *(uint32_t*)&p1);
    }
}

// ---------------- launcher ----------------
extern "C" void kernel_launch(void* const* d_in, const int* in_sizes, int n_in,
                              void* d_out, int out_size)
{
    (void)in_sizes; (void)n_in; (void)out_size;

    void *pah, *pwh, *pq, *pk, *pv, *px2;
    cudaGetSymbolAddress(&pah, g_ah);
    cudaGetSymbolAddress(&pwh, g_wh);
    cudaGetSymbolAddress(&pq,  g_q);
    cudaGetSymbolAddress(&pk,  g_k);
    cudaGetSymbolAddress(&pv,  g_v);
    cudaGetSymbolAddress(&px2, g_x2);

    __half* ah   = (__half*)pah;
    __half* wh   = (__half*)pwh;
    __half* qbuf = (__half*)pq;
    __half* kbuf = (__half*)pk;
    __half* vbuf = (__half*)pv;
    __half* x2   = (__half*)px2;

    cudaFuncSetAttribute(gemm_qkv, cudaFuncAttributeMaxDynamicSharedMemorySize, GEMM_SMEM);
    cudaFuncSetAttribute(gemm_out, cudaFuncAttributeMaxDynamicSharedMemorySize, GEMM_SMEM);

    // 1) convert activations (query/key/value) to fp16 — one launch
    const int actN8 = (int)(NELEM_ACT / 8);
    conv3_fp16_kernel<<<dim3(actN8 / 512, 3), 256>>>(
        (const float4*)d_in[0], (const float4*)d_in[1], (const float4*)d_in[2],
        (uint4*)ah, actN8);

    // 2) convert weights (Wq,Wk,Wv,Wo) to fp16 — one launch
    const int wN8 = (int)(NELEM_W / 8);
    conv4_fp16_kernel<<<dim3(wN8 / 256, 4), 256>>>(
        (const float4*)d_in[3], (const float4*)d_in[5],
        (const float4*)d_in[7], (const float4*)d_in[9],
        (uint4*)wh, wN8);

    // 3) Q+K+V projections in ONE launch (grid.z = 3); N-fastest for A reuse
    dim3 qkvgrid(DM / BN, MROWS / BM, 3);   // (8, 256, 3)
    gemm_qkv<<<qkvgrid, 128, GEMM_SMEM>>>(
        ah, wh,
        (const float*)d_in[4], (const float*)d_in[6], (const float*)d_in[8],
        qbuf, kbuf, vbuf);

    // 4) sparsemax attention (fp16 in) -> permuted X2 (fp16)
    attn_kernel<<<MROWS, 256>>>(qbuf, kbuf, vbuf, x2);

    // 5) output projection straight into d_out (fp32)
    dim3 ggrid(DM / BN, MROWS / BM);        // (8, 256)
    gemm_out<<<ggrid, 128, GEMM_SMEM>>>(
        x2, wh + 3 * NELEM_W, (const float*)d_in[10], (float*)d_out);
}

// round 12
// speedup vs baseline: 2.7965x; 1.0078x over previous
#include <cuda_runtime.h>
#include <cuda_fp16.h>
#include <cstdint>
#include <cstddef>

// ---------------- problem constants ----------------
#define SEQA   4096
#define BATCH  8
#define DM     1024
#define MROWS  (SEQA*BATCH)          // 32768
#define NELEM_ACT ((size_t)MROWS*DM) // 33554432
#define NELEM_W   ((size_t)DM*DM)    // 1048576

static __device__ __forceinline__ float inv_alpha() { return 1.0f/1.5f; }
#define SCORE_SCALE 0.125f           // 1/sqrt(64)

// ---------------- scratch (device globals; allocation-free) ----------------
__device__ __half g_ah[3][MROWS*DM];
__device__ __half g_wh[4][DM*DM];
__device__ __half g_q[MROWS*DM];
__device__ __half g_k[MROWS*DM];
__device__ __half g_v[MROWS*DM];
__device__ __half g_x2[MROWS*DM];

// ---------------- PTX helpers (baseline ISA only: sm_80-era) ----------------
__device__ __forceinline__ uint32_t smem_u32(const void* p) {
    uint32_t r;
    asm("{ .reg .u64 t; cvta.to.shared.u64 t, %1; cvt.u32.u64 %0, t; }"
        : "=r"(r) : "l"(p));
    return r;
}
__device__ __forceinline__ void cpasync16(uint32_t saddr, const void* g) {
    asm volatile("cp.async.cg.shared.global [%0], [%1], 16;"
                 :: "r"(saddr), "l"(g) : "memory");
}
__device__ __forceinline__ void cp_commit() {
    asm volatile("cp.async.commit_group;" ::: "memory");
}
template<int N> __device__ __forceinline__ void cp_wait() {
    asm volatile("cp.async.wait_group %0;" :: "n"(N) : "memory");
}
__device__ __forceinline__ void ldsm4(uint32_t* r, uint32_t addr) {
    asm volatile("ldmatrix.sync.aligned.m8n8.x4.shared.b16 {%0,%1,%2,%3}, [%4];"
                 : "=r"(r[0]), "=r"(r[1]), "=r"(r[2]), "=r"(r[3]) : "r"(addr));
}
__device__ __forceinline__ void mma16816(float* d, const uint32_t* a, const uint32_t* b) {
    asm volatile(
        "mma.sync.aligned.m16n8k16.row.col.f32.f16.f16.f32 "
        "{%0,%1,%2,%3}, {%4,%5,%6,%7}, {%8,%9}, {%0,%1,%2,%3};"
        : "+f"(d[0]), "+f"(d[1]), "+f"(d[2]), "+f"(d[3])
        : "r"(a[0]), "r"(a[1]), "r"(a[2]), "r"(a[3]), "r"(b[0]), "r"(b[1]));
}

// ---------------- conversion kernels: fp32 -> fp16 ----------------
__global__ void __launch_bounds__(256) conv3_fp16_kernel(
    const float4* __restrict__ x0, const float4* __restrict__ x1,
    const float4* __restrict__ x2,
    uint4* __restrict__ h, int n8)
{
    int i0 = (blockIdx.x * blockDim.x + threadIdx.x) * 2;
    if (i0 >= n8) return;
    const int w = blockIdx.y;
    const float4* x = (w == 0) ? x0 : (w == 1) ? x1 : x2;
    uint4* out = h + (size_t)w * n8;

#pragma unroll
    for (int e = 0; e < 2; e++) {
        int i = i0 + e;
        float4 a = x[2*i];
        float4 b = x[2*i+1];
        float v[8] = {a.x, a.y, a.z, a.w, b.x, b.y, b.z, b.w};
        uint32_t hw[4];
#pragma unroll
        for (int j = 0; j < 4; j++) {
            __half2 hp = __floats2half2_rn(v[2*j], v[2*j+1]);
            hw[j] = *reinterpret_cast<uint32_t*>(&hp);
        }
        out[i] = make_uint4(hw[0], hw[1], hw[2], hw[3]);
    }
}

__global__ void __launch_bounds__(256) conv4_fp16_kernel(
    const float4* __restrict__ w0, const float4* __restrict__ w1,
    const float4* __restrict__ w2, const float4* __restrict__ w3,
    uint4* __restrict__ h, int n8)
{
    int i = blockIdx.x * blockDim.x + threadIdx.x;
    if (i >= n8) return;
    const int w = blockIdx.y;
    const float4* x = (w == 0) ? w0 : (w == 1) ? w1 : (w == 2) ? w2 : w3;
    uint4* out = h + (size_t)w * n8;

    float4 a = x[2*i];
    float4 b = x[2*i+1];
    float v[8] = {a.x, a.y, a.z, a.w, b.x, b.y, b.z, b.w};
    uint32_t hw[4];
#pragma unroll
    for (int j = 0; j < 4; j++) {
        __half2 hp = __floats2half2_rn(v[2*j], v[2*j+1]);
        hw[j] = *reinterpret_cast<uint32_t*>(&hp);
    }
    out[i] = make_uint4(hw[0], hw[1], hw[2], hw[3]);
}

// ---------------- single-fp16 HMMA GEMM core (shared by both launchers) -----
#define BM 128
#define BN 128
#define BK 64
#define STAGES 3
#define AB_STAGE 16384                 // 128 rows x 128B (each of A and B)
#define GEMM_SMEM (STAGES * 2 * AB_STAGE)   // 98304
#define NCH 16                         // K=1024 / BK

template<int HALF_OUT>
__device__ __forceinline__ void gemm_core(
    const __half* __restrict__ Ah, const __half* __restrict__ Bh,
    const float* __restrict__ bias, void* __restrict__ Cv,
    char* smem, int bx, int by)
{
    const uint32_t sb = smem_u32(smem);
    const int tid  = threadIdx.x;
    const int lane = tid & 31;
    const int wid  = tid >> 5;        // 0..3
    const int wm   = wid >> 1;        // 0..1 (M 64 each)
    const int wn   = wid & 1;         // 0..1 (N 64 each)
    const int row0 = by * BM;
    const int col0 = bx * BN;         // N fastest-varying

    const int lr = tid >> 3;
    const int lc = tid & 7;

    float acc[4][8][4];
#pragma unroll
    for (int a = 0; a < 4; a++)
#pragma unroll
        for (int b = 0; b < 8; b++)
#pragma unroll
            for (int c = 0; c < 4; c++) acc[a][b][c] = 0.0f;

    auto load_stage = [&](int s, int ch) {
        const int ksub = ch * BK;
        const uint32_t sa  = sb + (uint32_t)s * 2 * AB_STAGE;
        const uint32_t sbB = sa + AB_STAGE;
#pragma unroll
        for (int rep = 0; rep < 8; rep++) {
            int r = lr + rep * 16;
            uint32_t sw = (uint32_t)(r * 128) + ((uint32_t)(lc ^ (r & 7)) << 4);
            cpasync16(sa  + sw, Ah + (size_t)(row0 + r) * DM + ksub + lc * 8);
            cpasync16(sbB + sw, Bh + (size_t)(col0 + r) * DM + ksub + lc * 8);
        }
    };

#pragma unroll
    for (int s = 0; s < STAGES - 1; s++) { load_stage(s, s); cp_commit(); }

    for (int ch = 0; ch < NCH; ch++) {
        cp_wait<STAGES - 2>();
        __syncthreads();

        const int nc = ch + STAGES - 1;
        if (nc < NCH) load_stage(nc % STAGES, nc);
        cp_commit();

        const int s = ch % STAGES;
        const uint32_t sa  = sb + (uint32_t)s * 2 * AB_STAGE;
        const uint32_t sbB = sa + AB_STAGE;

#pragma unroll
        for (int k16 = 0; k16 < 4; k16++) {
            uint32_t afrag[4][4];
#pragma unroll
            for (int mi = 0; mi < 4; mi++) {
                int r   = wm * 64 + mi * 16 + (lane & 15);
                int c16 = k16 * 2 + (lane >> 4);
                ldsm4(afrag[mi], sa + (uint32_t)(r * 128) + ((uint32_t)(c16 ^ (r & 7)) << 4));
            }
            uint32_t bfrag[4][4];
#pragma unroll
            for (int nb = 0; nb < 4; nb++) {
                int r   = wn * 64 + nb * 16 + (lane & 7) + ((lane & 16) ? 8 : 0);
                int c16 = k16 * 2 + ((lane >> 3) & 1);
                ldsm4(bfrag[nb], sbB + (uint32_t)(r * 128) + ((uint32_t)(c16 ^ (r & 7)) << 4));
            }
#pragma unroll
            for (int mi = 0; mi < 4; mi++)
#pragma unroll
                for (int ni = 0; ni < 8; ni++)
                    mma16816(acc[mi][ni], afrag[mi], &bfrag[ni >> 1][(ni & 1) * 2]);
        }
    }

    // ---- epilogue: bias add + store (fp16 or fp32) ----
    const int m_base = row0 + wm * 64;
    const int n_base = col0 + wn * 64;
    const int qr = lane >> 2;
    const int qc = (lane & 3) * 2;
#pragma unroll
    for (int ni = 0; ni < 8; ni++) {
        int colg = n_base + ni * 8 + qc;
        float bx2 = bias[colg], by2 = bias[colg + 1];
#pragma unroll
        for (int mi = 0; mi < 4; mi++) {
            int rg = m_base + mi * 16 + qr;
            float v00 = acc[mi][ni][0] + bx2, v01 = acc[mi][ni][1] + by2;
            float v10 = acc[mi][ni][2] + bx2, v11 = acc[mi][ni][3] + by2;
            if (HALF_OUT) {
                __half* C = (__half*)Cv;
                __half2 h0 = __floats2half2_rn(v00, v01);
                __half2 h1 = __floats2half2_rn(v10, v11);
                *(uint32_t*)(C + (size_t)rg * DM + colg)       = *(uint32_t*)&h0;
                *(uint32_t*)(C + (size_t)(rg + 8) * DM + colg) = *(uint32_t*)&h1;
            } else {
                float* C = (float*)Cv;
                *(float2*)(C + (size_t)rg * DM + colg)       = make_float2(v00, v01);
                *(float2*)(C + (size_t)(rg + 8) * DM + colg) = make_float2(v10, v11);
            }
        }
    }
}

// merged Q/K/V projection: grid.z = 3 selects (A, bias, C); one tail not three
__global__ void __launch_bounds__(128, 2) gemm_qkv(
    const __half* __restrict__ Ah0, const __half* __restrict__ Wh,
    const float* __restrict__ bq, const float* __restrict__ bk,
    const float* __restrict__ bv,
    __half* __restrict__ Cq, __half* __restrict__ Ck, __half* __restrict__ Cv2)
{
    extern __shared__ __align__(1024) char smem[];
    const int z = blockIdx.z;
    const __half* Ah = Ah0 + (size_t)z * NELEM_ACT;
    const __half* Bh = Wh  + (size_t)z * NELEM_W;
    const float* bias = (z == 0) ? bq : (z == 1) ? bk : bv;
    __half* C = (z == 0) ? Cq : (z == 1) ? Ck : Cv2;
    gemm_core<1>(Ah, Bh, bias, C, smem, blockIdx.x, blockIdx.y);
}

// final output projection (fp32 out)
__global__ void __launch_bounds__(128, 2) gemm_out(
    const __half* __restrict__ Ah, const __half* __restrict__ Bh,
    const float* __restrict__ bias, float* __restrict__ C)
{
    extern __shared__ __align__(1024) char smem[];
    gemm_core<0>(Ah, Bh, bias, C, smem, blockIdx.x, blockIdx.y);
}

// ---------------- head-mixing sparsemax attention (fp16 in, fp16 out) -------
// One block per (a,b) token. All smem access vectorized to 128-bit:
// K stored at stride 68 floats so LDS.128 across g=0..15 is phase-conflict-free
// (bank-group = g*17 mod 8 = g mod 8). FMA order matches the scalar version
// exactly (sequential x,y,z,w) so results are bit-identical.
#define KSTR 68
__global__ void __launch_bounds__(256) attn_kernel(
    const __half* __restrict__ Q, const __half* __restrict__ K,
    const __half* __restrict__ V, __half* __restrict__ x2)
{
    __shared__ float Qs[1024];
    __shared__ float Ks[16 * KSTR];
    __shared__ float Vs[1024];
    __shared__ float Ps[256];

    const int m = blockIdx.x;
    const int a = m >> 3, b = m & 7;
    const int t = threadIdx.x;

    // load rows: 256 threads x 4 halves (uint2) = 1024 elements each; float4 STS
    {
        int ci = t * 4;
        uint2 qu = ((const uint2*)(Q + (size_t)m * DM))[t];
        __half2 q0 = *(__half2*)&qu.x, q1 = *(__half2*)&qu.y;
        *(float4*)(Qs + ci) = make_float4(
            __low2float(q0), __high2float(q0), __low2float(q1), __high2float(q1));

        uint2 ku = ((const uint2*)(K + (size_t)m * DM))[t];
        __half2 k0 = *(__half2*)&ku.x, k1 = *(__half2*)&ku.y;
        int krow = ci >> 6, kcol = ci & 63;
        *(float4*)(Ks + krow * KSTR + kcol) = make_float4(
            __low2float(k0), __high2float(k0), __low2float(k1), __high2float(k1));

        uint2 vu = ((const uint2*)(V + (size_t)m * DM))[t];
        __half2 v0 = *(__half2*)&vu.x, v1 = *(__half2*)&vu.y;
        *(float4*)(Vs + ci) = make_float4(
            __low2float(v0), __high2float(v0), __low2float(v1), __high2float(v1));
    }
    __syncthreads();

    // scores: thread t -> (h = t/16, g = t%16); float4 LDS, sequential fmaf
    {
        int h = t >> 4, g = t & 15;
        const float4* qp = (const float4*)(Qs + h * 64);
        const float4* kp = (const float4*)(Ks + g * KSTR);
        float accv = 0.0f;
#pragma unroll
        for (int i = 0; i < 16; i++) {
            float4 q = qp[i];
            float4 k = kp[i];
            accv = fmaf(q.x, k.x, accv);
            accv = fmaf(q.y, k.y, accv);
            accv = fmaf(q.z, k.z, accv);
            accv = fmaf(q.w, k.w, accv);
        }
        Ps[t] = accv * SCORE_SCALE;
    }
    __syncthreads();

    // sparsemax over the 16 scores of head t (threads 0..15)
    if (t < 16) {
        float z[16];
#pragma unroll
        for (int i = 0; i < 16; i++) z[i] = Ps[t * 16 + i] * inv_alpha();
#pragma unroll
        for (int k = 2; k <= 16; k <<= 1) {
#pragma unroll
            for (int j = k >> 1; j > 0; j >>= 1) {
#pragma unroll
                for (int i = 0; i < 16; i++) {
                    int l = i ^ j;
                    if (l > i) {
                        bool up = ((i & k) == 0);
                        float zi = z[i], zl = z[l];
                        bool sw = up ? (zi > zl) : (zi < zl);
                        if (sw) { z[i] = zl; z[l] = zi; }
                    }
                }
            }
        }
        float cum = 0.0f, csel = 0.0f;
        int kc = 1;
#pragma unroll
        for (int r = 1; r <= 16; r++) {
            float v = z[16 - r];
            cum += v;
            if (v * (float)r > cum - 1.0f) { kc = r; csel = cum; }
        }
        float tau = (csel - 1.0f) / (float)kc;
#pragma unroll
        for (int i = 0; i < 16; i++) {
            float p = Ps[t * 16 + i] * inv_alpha() - tau;
            Ps[t * 16 + i] = p > 0.0f ? p : 0.0f;
        }
    }
    __syncthreads();

    // AV: thread t -> (h = t/16, d-base = (t%16)*4); float4 V loads
    {
        int h = t >> 4;
        int db = (t & 15) * 4;
        float o0 = 0, o1 = 0, o2 = 0, o3 = 0;
#pragma unroll
        for (int g = 0; g < 16; g++) {
            float p = Ps[h * 16 + g];
            float4 v = *(const float4*)(Vs + g * 64 + db);
            o0 = fmaf(p, v.x, o0);
            o1 = fmaf(p, v.y, o1);
            o2 = fmaf(p, v.z, o2);
            o3 = fmaf(p, v.w, o3);
        }
        size_t m2  = ((size_t)(h * 256 + (a >> 4))) * 8 + (size_t)b;
        int    col = (a & 15) * 64 + db;
        __half2 p0 = __floats2half2_rn(o0, o1);
        __half2 p1 = __floats2half2_rn(o2, o3);
        *(uint2*)(x2 + m2 * DM + col) =
            make_uint2(*(uint32_t*)&p0, *(uint32_t*)&p1);
    }
}

// ---------------- launcher ----------------
extern "C" void kernel_launch(void* const* d_in, const int* in_sizes, int n_in,
                              void* d_out, int out_size)
{
    (void)in_sizes; (void)n_in; (void)out_size;

    void *pah, *pwh, *pq, *pk, *pv, *px2;
    cudaGetSymbolAddress(&pah, g_ah);
    cudaGetSymbolAddress(&pwh, g_wh);
    cudaGetSymbolAddress(&pq,  g_q);
    cudaGetSymbolAddress(&pk,  g_k);
    cudaGetSymbolAddress(&pv,  g_v);
    cudaGetSymbolAddress(&px2, g_x2);

    __half* ah   = (__half*)pah;
    __half* wh   = (__half*)pwh;
    __half* qbuf = (__half*)pq;
    __half* kbuf = (__half*)pk;
    __half* vbuf = (__half*)pv;
    __half* x2   = (__half*)px2;

    cudaFuncSetAttribute(gemm_qkv, cudaFuncAttributeMaxDynamicSharedMemorySize, GEMM_SMEM);
    cudaFuncSetAttribute(gemm_out, cudaFuncAttributeMaxDynamicSharedMemorySize, GEMM_SMEM);

    // 1) convert activations (query/key/value) to fp16 — one launch
    const int actN8 = (int)(NELEM_ACT / 8);
    conv3_fp16_kernel<<<dim3(actN8 / 512, 3), 256>>>(
        (const float4*)d_in[0], (const float4*)d_in[1], (const float4*)d_in[2],
        (uint4*)ah, actN8);

    // 2) convert weights (Wq,Wk,Wv,Wo) to fp16 — one launch
    const int wN8 = (int)(NELEM_W / 8);
    conv4_fp16_kernel<<<dim3(wN8 / 256, 4), 256>>>(
        (const float4*)d_in[3], (const float4*)d_in[5],
        (const float4*)d_in[7], (const float4*)d_in[9],
        (uint4*)wh, wN8);

    // 3) Q+K+V projections in ONE launch (grid.z = 3); N-fastest for A reuse
    dim3 qkvgrid(DM / BN, MROWS / BM, 3);   // (8, 256, 3)
    gemm_qkv<<<qkvgrid, 128, GEMM_SMEM>>>(
        ah, wh,
        (const float*)d_in[4], (const float*)d_in[6], (const float*)d_in[8],
        qbuf, kbuf, vbuf);

    // 4) sparsemax attention (fp16 in) -> permuted X2 (fp16)
    attn_kernel<<<MROWS, 256>>>(qbuf, kbuf, vbuf, x2);

    // 5) output projection straight into d_out (fp32)
    dim3 ggrid(DM / BN, MROWS / BM);        // (8, 256)
    gemm_out<<<ggrid, 128, GEMM_SMEM>>>(
        x2, wh + 3 * NELEM_W, (const float*)d_in[10], (float*)d_out);
}

// round 13
// speedup vs baseline: 3.0512x; 1.0911x over previous
#include <cuda_runtime.h>
#include <cuda_fp16.h>
#include <cstdint>
#include <cstddef>

// ---------------- problem constants ----------------
#define SEQA   4096
#define BATCH  8
#define DM     1024
#define MROWS  (SEQA*BATCH)          // 32768
#define NELEM_ACT ((size_t)MROWS*DM) // 33554432
#define NELEM_W   ((size_t)DM*DM)    // 1048576

static __device__ __forceinline__ float inv_alpha() { return 1.0f/1.5f; }
#define SCORE_SCALE 0.125f           // 1/sqrt(64)

// ---------------- scratch (device globals; allocation-free) ----------------
__device__ __half g_ah[3][MROWS*DM];
__device__ __half g_wh[4][DM*DM];
__device__ __half g_q[MROWS*DM];
__device__ __half g_k[MROWS*DM];
__device__ __half g_v[MROWS*DM];
__device__ __half g_x2[MROWS*DM];

// ---------------- PTX helpers (baseline ISA only: sm_80-era) ----------------
__device__ __forceinline__ uint32_t smem_u32(const void* p) {
    uint32_t r;
    asm("{ .reg .u64 t; cvta.to.shared.u64 t, %1; cvt.u32.u64 %0, t; }"
        : "=r"(r) : "l"(p));
    return r;
}
__device__ __forceinline__ void cpasync16(uint32_t saddr, const void* g) {
    asm volatile("cp.async.cg.shared.global [%0], [%1], 16;"
                 :: "r"(saddr), "l"(g) : "memory");
}
__device__ __forceinline__ void cp_commit() {
    asm volatile("cp.async.commit_group;" ::: "memory");
}
template<int N> __device__ __forceinline__ void cp_wait() {
    asm volatile("cp.async.wait_group %0;" :: "n"(N) : "memory");
}
__device__ __forceinline__ void ldsm4(uint32_t* r, uint32_t addr) {
    asm volatile("ldmatrix.sync.aligned.m8n8.x4.shared.b16 {%0,%1,%2,%3}, [%4];"
                 : "=r"(r[0]), "=r"(r[1]), "=r"(r[2]), "=r"(r[3]) : "r"(addr));
}
__device__ __forceinline__ void mma16816(float* d, const uint32_t* a, const uint32_t* b) {
    asm volatile(
        "mma.sync.aligned.m16n8k16.row.col.f32.f16.f16.f32 "
        "{%0,%1,%2,%3}, {%4,%5,%6,%7}, {%8,%9}, {%0,%1,%2,%3};"
        : "+f"(d[0]), "+f"(d[1]), "+f"(d[2]), "+f"(d[3])
        : "r"(a[0]), "r"(a[1]), "r"(a[2]), "r"(a[3]), "r"(b[0]), "r"(b[1]));
}

// ---------------- conversion kernels: fp32 -> fp16 ----------------
__global__ void __launch_bounds__(256) conv3_fp16_kernel(
    const float4* __restrict__ x0, const float4* __restrict__ x1,
    const float4* __restrict__ x2,
    uint4* __restrict__ h, int n8)
{
    int i0 = (blockIdx.x * blockDim.x + threadIdx.x) * 2;
    if (i0 >= n8) return;
    const int w = blockIdx.y;
    const float4* x = (w == 0) ? x0 : (w == 1) ? x1 : x2;
    uint4* out = h + (size_t)w * n8;

#pragma unroll
    for (int e = 0; e < 2; e++) {
        int i = i0 + e;
        float4 a = x[2*i];
        float4 b = x[2*i+1];
        float v[8] = {a.x, a.y, a.z, a.w, b.x, b.y, b.z, b.w};
        uint32_t hw[4];
#pragma unroll
        for (int j = 0; j < 4; j++) {
            __half2 hp = __floats2half2_rn(v[2*j], v[2*j+1]);
            hw[j] = *reinterpret_cast<uint32_t*>(&hp);
        }
        out[i] = make_uint4(hw[0], hw[1], hw[2], hw[3]);
    }
}

__global__ void __launch_bounds__(256) conv4_fp16_kernel(
    const float4* __restrict__ w0, const float4* __restrict__ w1,
    const float4* __restrict__ w2, const float4* __restrict__ w3,
    uint4* __restrict__ h, int n8)
{
    int i = blockIdx.x * blockDim.x + threadIdx.x;
    if (i >= n8) return;
    const int w = blockIdx.y;
    const float4* x = (w == 0) ? w0 : (w == 1) ? w1 : (w == 2) ? w2 : w3;
    uint4* out = h + (size_t)w * n8;

    float4 a = x[2*i];
    float4 b = x[2*i+1];
    float v[8] = {a.x, a.y, a.z, a.w, b.x, b.y, b.z, b.w};
    uint32_t hw[4];
#pragma unroll
    for (int j = 0; j < 4; j++) {
        __half2 hp = __floats2half2_rn(v[2*j], v[2*j+1]);
        hw[j] = *reinterpret_cast<uint32_t*>(&hp);
    }
    out[i] = make_uint4(hw[0], hw[1], hw[2], hw[3]);
}

// ---------------- single-fp16 HMMA GEMM core (shared by both launchers) -----
#define BM 128
#define BN 128
#define BK 64
#define STAGES 3
#define AB_STAGE 16384                 // 128 rows x 128B (each of A and B)
#define GEMM_SMEM (STAGES * 2 * AB_STAGE)   // 98304
#define NCH 16                         // K=1024 / BK

template<int HALF_OUT>
__device__ __forceinline__ void gemm_core(
    const __half* __restrict__ Ah, const __half* __restrict__ Bh,
    const float* __restrict__ bias, void* __restrict__ Cv,
    char* smem, int bx, int by)
{
    const uint32_t sb = smem_u32(smem);
    const int tid  = threadIdx.x;
    const int lane = tid & 31;
    const int wid  = tid >> 5;        // 0..3
    const int wm   = wid >> 1;        // 0..1 (M 64 each)
    const int wn   = wid & 1;         // 0..1 (N 64 each)
    const int row0 = by * BM;
    const int col0 = bx * BN;         // N fastest-varying

    const int lr = tid >> 3;
    const int lc = tid & 7;

    float acc[4][8][4];
#pragma unroll
    for (int a = 0; a < 4; a++)
#pragma unroll
        for (int b = 0; b < 8; b++)
#pragma unroll
            for (int c = 0; c < 4; c++) acc[a][b][c] = 0.0f;

    auto load_stage = [&](int s, int ch) {
        const int ksub = ch * BK;
        const uint32_t sa  = sb + (uint32_t)s * 2 * AB_STAGE;
        const uint32_t sbB = sa + AB_STAGE;
#pragma unroll
        for (int rep = 0; rep < 8; rep++) {
            int r = lr + rep * 16;
            uint32_t sw = (uint32_t)(r * 128) + ((uint32_t)(lc ^ (r & 7)) << 4);
            cpasync16(sa  + sw, Ah + (size_t)(row0 + r) * DM + ksub + lc * 8);
            cpasync16(sbB + sw, Bh + (size_t)(col0 + r) * DM + ksub + lc * 8);
        }
    };

#pragma unroll
    for (int s = 0; s < STAGES - 1; s++) { load_stage(s, s); cp_commit(); }

    for (int ch = 0; ch < NCH; ch++) {
        cp_wait<STAGES - 2>();
        __syncthreads();

        const int nc = ch + STAGES - 1;
        if (nc < NCH) load_stage(nc % STAGES, nc);
        cp_commit();

        const int s = ch % STAGES;
        const uint32_t sa  = sb + (uint32_t)s * 2 * AB_STAGE;
        const uint32_t sbB = sa + AB_STAGE;

#pragma unroll
        for (int k16 = 0; k16 < 4; k16++) {
            uint32_t afrag[4][4];
#pragma unroll
            for (int mi = 0; mi < 4; mi++) {
                int r   = wm * 64 + mi * 16 + (lane & 15);
                int c16 = k16 * 2 + (lane >> 4);
                ldsm4(afrag[mi], sa + (uint32_t)(r * 128) + ((uint32_t)(c16 ^ (r & 7)) << 4));
            }
            uint32_t bfrag[4][4];
#pragma unroll
            for (int nb = 0; nb < 4; nb++) {
                int r   = wn * 64 + nb * 16 + (lane & 7) + ((lane & 16) ? 8 : 0);
                int c16 = k16 * 2 + ((lane >> 3) & 1);
                ldsm4(bfrag[nb], sbB + (uint32_t)(r * 128) + ((uint32_t)(c16 ^ (r & 7)) << 4));
            }
#pragma unroll
            for (int mi = 0; mi < 4; mi++)
#pragma unroll
                for (int ni = 0; ni < 8; ni++)
                    mma16816(acc[mi][ni], afrag[mi], &bfrag[ni >> 1][(ni & 1) * 2]);
        }
    }

    // ---- epilogue: bias add + store (fp16 or fp32) ----
    const int m_base = row0 + wm * 64;
    const int n_base = col0 + wn * 64;
    const int qr = lane >> 2;
    const int qc = (lane & 3) * 2;
#pragma unroll
    for (int ni = 0; ni < 8; ni++) {
        int colg = n_base + ni * 8 + qc;
        float bx2 = bias[colg], by2 = bias[colg + 1];
#pragma unroll
        for (int mi = 0; mi < 4; mi++) {
            int rg = m_base + mi * 16 + qr;
            float v00 = acc[mi][ni][0] + bx2, v01 = acc[mi][ni][1] + by2;
            float v10 = acc[mi][ni][2] + bx2, v11 = acc[mi][ni][3] + by2;
            if (HALF_OUT) {
                __half* C = (__half*)Cv;
                __half2 h0 = __floats2half2_rn(v00, v01);
                __half2 h1 = __floats2half2_rn(v10, v11);
                *(uint32_t*)(C + (size_t)rg * DM + colg)       = *(uint32_t*)&h0;
                *(uint32_t*)(C + (size_t)(rg + 8) * DM + colg) = *(uint32_t*)&h1;
            } else {
                float* C = (float*)Cv;
                *(float2*)(C + (size_t)rg * DM + colg)       = make_float2(v00, v01);
                *(float2*)(C + (size_t)(rg + 8) * DM + colg) = make_float2(v10, v11);
            }
        }
    }
}

// merged Q/K/V projection: grid.z = 3 selects (A, bias, C); one tail not three
__global__ void __launch_bounds__(128, 2) gemm_qkv(
    const __half* __restrict__ Ah0, const __half* __restrict__ Wh,
    const float* __restrict__ bq, const float* __restrict__ bk,
    const float* __restrict__ bv,
    __half* __restrict__ Cq, __half* __restrict__ Ck, __half* __restrict__ Cv2)
{
    extern __shared__ __align__(1024) char smem[];
    const int z = blockIdx.z;
    const __half* Ah = Ah0 + (size_t)z * NELEM_ACT;
    const __half* Bh = Wh  + (size_t)z * NELEM_W;
    const float* bias = (z == 0) ? bq : (z == 1) ? bk : bv;
    __half* C = (z == 0) ? Cq : (z == 1) ? Ck : Cv2;
    gemm_core<1>(Ah, Bh, bias, C, smem, blockIdx.x, blockIdx.y);
}

// final output projection (fp32 out)
__global__ void __launch_bounds__(128, 2) gemm_out(
    const __half* __restrict__ Ah, const __half* __restrict__ Bh,
    const float* __restrict__ bias, float* __restrict__ C)
{
    extern __shared__ __align__(1024) char smem[];
    gemm_core<0>(Ah, Bh, bias, C, smem, blockIdx.x, blockIdx.y);
}

// ---------------- head-mixing sparsemax attention, tensor-core scores -------
// ONE WARP PER TOKEN (8 tokens/block). Scores S[16,16] = Q(16x64) @ K(16x64)^T
// via mma.m16n8k16 (fragment addressing identical to the proven GEMM core,
// 144B-padded rows, no swizzle needed). Sparsemax on fp32 P tile (stride 17).
// AV stays scalar fp32 with the ORIGINAL fmaf order (bit-identical given P,V);
// lane -> (h = lane&15, d-window = lane>>4) so V float4 loads are same-address
// broadcasts within each crossbar phase (V bytes ~free).
// Per-warp smem: Qt 16x72 fp16 (2304B) | Kt 2304B | Vt 16x68 fp32 (4352B)
//                | Ps 16x17 fp32 (1088B)  -> 10240B span, 8 warps = 80KB.
#define AT_WSPAN 10240
#define ATT_SMEM (8 * AT_WSPAN)
__global__ void __launch_bounds__(256) attn_kernel(
    const __half* __restrict__ Q, const __half* __restrict__ K,
    const __half* __restrict__ V, __half* __restrict__ x2)
{
    extern __shared__ __align__(1024) char asmem[];
    const int lane = threadIdx.x & 31;
    const int wid  = threadIdx.x >> 5;
    const int m = blockIdx.x * 8 + wid;
    const int a = m >> 3, b = m & 7;

    char* ws = asmem + wid * AT_WSPAN;
    __half* Qt = (__half*)ws;              // 16 rows x 72 halves (144B rows)
    __half* Kt = (__half*)(ws + 2304);     // 16 rows x 72 halves
    float*  Vt = (float*)(ws + 4608);      // 16 rows x 68 floats (272B rows)
    float*  Ps = (float*)(ws + 8960);      // 16 x 17 floats

    // ---- fill: lane covers halves [lane*32, lane*32+32) of each 1024-row ----
    {
        const int r  = lane >> 1;            // row 0..15
        const int cb = (lane & 1) * 32;      // col base 0/32
        const uint4* qg = (const uint4*)(Q + (size_t)m * DM);
        const uint4* kg = (const uint4*)(K + (size_t)m * DM);
        const uint4* vg = (const uint4*)(V + (size_t)m * DM);
#pragma unroll
        for (int j = 0; j < 4; j++) {
            *(uint4*)(Qt + r * 72 + cb + j * 8) = qg[lane * 4 + j];
            *(uint4*)(Kt + r * 72 + cb + j * 8) = kg[lane * 4 + j];
            uint4 vv = vg[lane * 4 + j];
            __half2 h0 = *(__half2*)&vv.x, h1 = *(__half2*)&vv.y;
            __half2 h2 = *(__half2*)&vv.z, h3 = *(__half2*)&vv.w;
            *(float4*)(Vt + r * 68 + cb + j * 8) = make_float4(
                __low2float(h0), __high2float(h0), __low2float(h1), __high2float(h1));
            *(float4*)(Vt + r * 68 + cb + j * 8 + 4) = make_float4(
                __low2float(h2), __high2float(h2), __low2float(h3), __high2float(h3));
        }
    }
    __syncwarp();

    // ---- scores via mma: S = Q @ K^T (m16 n16 k64) ----
    {
        const uint32_t sQ = smem_u32(Qt);
        const uint32_t sK = smem_u32(Kt);
        const int ar = lane & 15, ac = lane >> 4;
        const int br = (lane & 7) + ((lane & 16) ? 8 : 0);
        const int bc = (lane >> 3) & 1;
        float S0[4] = {0, 0, 0, 0};
        float S1[4] = {0, 0, 0, 0};
#pragma unroll
        for (int k16 = 0; k16 < 4; k16++) {
            uint32_t af[4], bf[4];
            ldsm4(af, sQ + (uint32_t)(ar * 144) + (uint32_t)(k16 * 2 + ac) * 16);
            ldsm4(bf, sK + (uint32_t)(br * 144) + (uint32_t)(k16 * 2 + bc) * 16);
            mma16816(S0, af, &bf[0]);
            mma16816(S1, af, &bf[2]);
        }
        const int qr = lane >> 2;
        const int qc = (lane & 3) * 2;
        Ps[qr * 17 + qc]           = S0[0] * SCORE_SCALE;
        Ps[qr * 17 + qc + 1]       = S0[1] * SCORE_SCALE;
        Ps[(qr + 8) * 17 + qc]     = S0[2] * SCORE_SCALE;
        Ps[(qr + 8) * 17 + qc + 1] = S0[3] * SCORE_SCALE;
        Ps[qr * 17 + 8 + qc]           = S1[0] * SCORE_SCALE;
        Ps[qr * 17 + 8 + qc + 1]       = S1[1] * SCORE_SCALE;
        Ps[(qr + 8) * 17 + 8 + qc]     = S1[2] * SCORE_SCALE;
        Ps[(qr + 8) * 17 + 8 + qc + 1] = S1[3] * SCORE_SCALE;
    }
    __syncwarp();

    // ---- sparsemax over each head's 16 scores (lanes 0..15) ----
    if (lane < 16) {
        float z[16];
#pragma unroll
        for (int i = 0; i < 16; i++) z[i] = Ps[lane * 17 + i] * inv_alpha();
#pragma unroll
        for (int k = 2; k <= 16; k <<= 1) {
#pragma unroll
            for (int j = k >> 1; j > 0; j >>= 1) {
#pragma unroll
                for (int i = 0; i < 16; i++) {
                    int l = i ^ j;
                    if (l > i) {
                        bool up = ((i & k) == 0);
                        float zi = z[i], zl = z[l];
                        bool sw = up ? (zi > zl) : (zi < zl);
                        if (sw) { z[i] = zl; z[l] = zi; }
                    }
                }
            }
        }
        float cum = 0.0f, csel = 0.0f;
        int kc = 1;
#pragma unroll
        for (int r = 1; r <= 16; r++) {
            float v = z[16 - r];
            cum += v;
            if (v * (float)r > cum - 1.0f) { kc = r; csel = cum; }
        }
        float tau = (csel - 1.0f) / (float)kc;
#pragma unroll
        for (int i = 0; i < 16; i++) {
            float p = Ps[lane * 17 + i] * inv_alpha() - tau;
            Ps[lane * 17 + i] = p > 0.0f ? p : 0.0f;
        }
    }
    __syncwarp();

    // ---- AV: lane -> (h = lane&15, d-window = (lane>>4)*32); original order --
    {
        const int h  = lane & 15;
        const int dw = (lane >> 4) * 32;
        float o[32];
#pragma unroll
        for (int j = 0; j < 32; j++) o[j] = 0.0f;
#pragma unroll
        for (int g = 0; g < 16; g++) {
            float p = Ps[h * 17 + g];
            const float4* vr = (const float4*)(Vt + g * 68 + dw);
#pragma unroll
            for (int j = 0; j < 8; j++) {
                float4 v = vr[j];
                o[j*4 + 0] = fmaf(p, v.x, o[j*4 + 0]);
                o[j*4 + 1] = fmaf(p, v.y, o[j*4 + 1]);
                o[j*4 + 2] = fmaf(p, v.z, o[j*4 + 2]);
                o[j*4 + 3] = fmaf(p, v.w, o[j*4 + 3]);
            }
        }
        const size_t m2  = ((size_t)(h * 256 + (a >> 4))) * 8 + (size_t)b;
        const int    col = (a & 15) * 64 + dw;
        __half* dst = x2 + m2 * DM + col;
#pragma unroll
        for (int j = 0; j < 8; j++) {
            __half2 p0 = __floats2half2_rn(o[j*4 + 0], o[j*4 + 1]);
            __half2 p1 = __floats2half2_rn(o[j*4 + 2], o[j*4 + 3]);
            *(uint2*)(dst + j * 4) = make_uint2(*(uint32_t*)&p0, *(uint32_t*)&p1);
        }
    }
}

// ---------------- launcher ----------------
extern "C" void kernel_launch(void* const* d_in, const int* in_sizes, int n_in,
                              void* d_out, int out_size)
{
    (void)in_sizes; (void)n_in; (void)out_size;

    void *pah, *pwh, *pq, *pk, *pv, *px2;
    cudaGetSymbolAddress(&pah, g_ah);
    cudaGetSymbolAddress(&pwh, g_wh);
    cudaGetSymbolAddress(&pq,  g_q);
    cudaGetSymbolAddress(&pk,  g_k);
    cudaGetSymbolAddress(&pv,  g_v);
    cudaGetSymbolAddress(&px2, g_x2);

    __half* ah   = (__half*)pah;
    __half* wh   = (__half*)pwh;
    __half* qbuf = (__half*)pq;
    __half* kbuf = (__half*)pk;
    __half* vbuf = (__half*)pv;
    __half* x2   = (__half*)px2;

    cudaFuncSetAttribute(gemm_qkv, cudaFuncAttributeMaxDynamicSharedMemorySize, GEMM_SMEM);
    cudaFuncSetAttribute(gemm_out, cudaFuncAttributeMaxDynamicSharedMemorySize, GEMM_SMEM);
    cudaFuncSetAttribute(attn_kernel, cudaFuncAttributeMaxDynamicSharedMemorySize, ATT_SMEM);

    // 1) convert activations (query/key/value) to fp16 — one launch
    const int actN8 = (int)(NELEM_ACT / 8);
    conv3_fp16_kernel<<<dim3(actN8 / 512, 3), 256>>>(
        (const float4*)d_in[0], (const float4*)d_in[1], (const float4*)d_in[2],
        (uint4*)ah, actN8);

    // 2) convert weights (Wq,Wk,Wv,Wo) to fp16 — one launch
    const int wN8 = (int)(NELEM_W / 8);
    conv4_fp16_kernel<<<dim3(wN8 / 256, 4), 256>>>(
        (const float4*)d_in[3], (const float4*)d_in[5],
        (const float4*)d_in[7], (const float4*)d_in[9],
        (uint4*)wh, wN8);

    // 3) Q+K+V projections in ONE launch (grid.z = 3); N-fastest for A reuse
    dim3 qkvgrid(DM / BN, MROWS / BM, 3);   // (8, 256, 3)
    gemm_qkv<<<qkvgrid, 128, GEMM_SMEM>>>(
        ah, wh,
        (const float*)d_in[4], (const float*)d_in[6], (const float*)d_in[8],
        qbuf, kbuf, vbuf);

    // 4) sparsemax attention (tensor-core scores) -> permuted X2 (fp16)
    attn_kernel<<<MROWS / 8, 256, ATT_SMEM>>>(qbuf, kbuf, vbuf, x2);

    // 5) output projection straight into d_out (fp32)
    dim3 ggrid(DM / BN, MROWS / BM);        // (8, 256)
    gemm_out<<<ggrid, 128, GEMM_SMEM>>>(
        x2, wh + 3 * NELEM_W, (const float*)d_in[10], (float*)d_out);
}